// round 1
// baseline (speedup 1.0000x reference)
#include <cuda_runtime.h>
#include <math_constants.h>

#define BB 8
#define TT 2048
#define CC 1024
#define HH 128

// Scratch for projected q, k, v: [B*T, H] each (allocation-free rule -> device globals)
__device__ float g_q[BB*TT*HH];
__device__ float g_k[BB*TT*HH];
__device__ float g_v[BB*TT*HH];

// ---------------------------------------------------------------------------
// Kernel 1: QKV projection. grid=(256,3), block=256
// out[rb*64 .. rb*64+63][0..127] = x_tile @ W  (one of Wq/Wk/Wv per blockIdx.y)
// ---------------------------------------------------------------------------
__global__ __launch_bounds__(256) void qkv_kernel(const float* __restrict__ x,
                                                  const float* __restrict__ Wq,
                                                  const float* __restrict__ Wk,
                                                  const float* __restrict__ Wv) {
    __shared__ float xs[64 * 36];    // 64 rows x 32 k, pitch 36 (16B-aligned rows)
    __shared__ float ws[32 * 128];   // 32 k x 128 cols

    const int tid = threadIdx.x;
    const int ty = tid >> 4;         // 0..15 -> 4 rows each
    const int tx = tid & 15;         // 0..15 -> 8 cols each
    const int rb = blockIdx.x;

    const float* W;
    float* out;
    if (blockIdx.y == 0)      { W = Wq; out = g_q; }
    else if (blockIdx.y == 1) { W = Wk; out = g_k; }
    else                      { W = Wv; out = g_v; }

    float acc[4][8];
#pragma unroll
    for (int i = 0; i < 4; i++)
#pragma unroll
        for (int c = 0; c < 8; c++) acc[i][c] = 0.0f;

    const float* xbase = x + (size_t)rb * 64 * CC;

    for (int k0 = 0; k0 < CC; k0 += 32) {
        __syncthreads();
        // load x tile [64][32]
#pragma unroll
        for (int i = 0; i < 2; i++) {
            int f = tid + i * 256;          // 0..511 float4
            int row = f >> 3, kq = f & 7;
            float4 v = *(const float4*)(xbase + (size_t)row * CC + k0 + kq * 4);
            *(float4*)(xs + row * 36 + kq * 4) = v;
        }
        // load W tile [32][128]
#pragma unroll
        for (int i = 0; i < 4; i++) {
            int f = tid + i * 256;          // 0..1023 float4
            int row = f >> 5, cq = f & 31;
            *(float4*)(ws + row * 128 + cq * 4) =
                *(const float4*)(W + (size_t)(k0 + row) * HH + cq * 4);
        }
        __syncthreads();

#pragma unroll
        for (int kk = 0; kk < 32; kk++) {
            float4 b0 = *(const float4*)(ws + kk * 128 + tx * 8);
            float4 b1 = *(const float4*)(ws + kk * 128 + tx * 8 + 4);
#pragma unroll
            for (int i = 0; i < 4; i++) {
                float a = xs[(ty * 4 + i) * 36 + kk];
                acc[i][0] += a * b0.x; acc[i][1] += a * b0.y;
                acc[i][2] += a * b0.z; acc[i][3] += a * b0.w;
                acc[i][4] += a * b1.x; acc[i][5] += a * b1.y;
                acc[i][6] += a * b1.z; acc[i][7] += a * b1.w;
            }
        }
    }

#pragma unroll
    for (int i = 0; i < 4; i++) {
        size_t row = (size_t)rb * 64 + ty * 4 + i;
        *(float4*)(out + row * HH + tx * 8) =
            make_float4(acc[i][0], acc[i][1], acc[i][2], acc[i][3]);
        *(float4*)(out + row * HH + tx * 8 + 4) =
            make_float4(acc[i][4], acc[i][5], acc[i][6], acc[i][7]);
    }
}

// ---------------------------------------------------------------------------
// Kernel 2: fused flash attention (no mask). grid=256 (8 batches x 32 q-tiles),
// block=256. BM=64 q rows, BN=64 keys/iter, D=128.
// smem: Qs[128][68] d-major, KVs (K d-major [128][68] OR V row-major [64][128]),
//       Ps[64][68].  Total 87040 B -> 2 blocks/SM.
// ---------------------------------------------------------------------------
#define PITCH 68
#define QS_FLOATS (128 * PITCH)
#define PS_FLOATS (64 * PITCH)
#define ATTN_SMEM_BYTES ((2 * QS_FLOATS + PS_FLOATS) * 4)

__global__ __launch_bounds__(256) void attn_kernel(float* __restrict__ out) {
    extern __shared__ float sm[];
    float* Qs  = sm;                 // [128][68] (d-major)
    float* KVs = sm + QS_FLOATS;     // K: [128][68] d-major, then V: [64][128] row-major
    float* Ps  = sm + 2 * QS_FLOATS; // [64][68]

    const int tid = threadIdx.x;
    const int ty = tid >> 4;   // 0..15 -> 4 q rows
    const int tx = tid & 15;   // 0..15 -> 4 s-cols / 8 o-cols
    const int b  = blockIdx.x >> 5;
    const int qt = blockIdx.x & 31;

    const float* qg = g_q + ((size_t)b * TT + qt * 64) * HH;
    const float* kg = g_k + (size_t)b * TT * HH;
    const float* vg = g_v + (size_t)b * TT * HH;

    // Load Q tile transposed (d-major), folding the 1/sqrt(C)=1/32 scale
#pragma unroll
    for (int i = 0; i < 8; i++) {
        int f = tid + i * 256;          // 2048 float4
        int row = f >> 5, dq = f & 31;
        float4 v = *(const float4*)(qg + (size_t)row * HH + dq * 4);
        Qs[(dq * 4 + 0) * PITCH + row] = v.x * 0.03125f;
        Qs[(dq * 4 + 1) * PITCH + row] = v.y * 0.03125f;
        Qs[(dq * 4 + 2) * PITCH + row] = v.z * 0.03125f;
        Qs[(dq * 4 + 3) * PITCH + row] = v.w * 0.03125f;
    }

    float m[4], l[4], O[4][8];
#pragma unroll
    for (int i = 0; i < 4; i++) {
        m[i] = -CUDART_INF_F;
        l[i] = 0.0f;
#pragma unroll
        for (int c = 0; c < 8; c++) O[i][c] = 0.0f;
    }

    for (int kt = 0; kt < TT / 64; kt++) {
        const float* kb = kg + (size_t)kt * 64 * HH;
        const float* vb = vg + (size_t)kt * 64 * HH;

        __syncthreads();   // protect KVs reuse from previous iteration's reads
        // Load K tile transposed (d-major)
#pragma unroll
        for (int i = 0; i < 8; i++) {
            int f = tid + i * 256;
            int row = f >> 5, dq = f & 31;
            float4 v = *(const float4*)(kb + (size_t)row * HH + dq * 4);
            KVs[(dq * 4 + 0) * PITCH + row] = v.x;
            KVs[(dq * 4 + 1) * PITCH + row] = v.y;
            KVs[(dq * 4 + 2) * PITCH + row] = v.z;
            KVs[(dq * 4 + 3) * PITCH + row] = v.w;
        }
        __syncthreads();

        // S[4][4] = Q_tile @ K_tile^T  (scaled via Q)
        float S[4][4];
#pragma unroll
        for (int i = 0; i < 4; i++)
#pragma unroll
            for (int j = 0; j < 4; j++) S[i][j] = 0.0f;

#pragma unroll 4
        for (int d = 0; d < HH; d++) {
            float4 qv = *(const float4*)(Qs + d * PITCH + ty * 4);
            float4 kv = *(const float4*)(KVs + d * PITCH + tx * 4);
            S[0][0] += qv.x * kv.x; S[0][1] += qv.x * kv.y; S[0][2] += qv.x * kv.z; S[0][3] += qv.x * kv.w;
            S[1][0] += qv.y * kv.x; S[1][1] += qv.y * kv.y; S[1][2] += qv.y * kv.z; S[1][3] += qv.y * kv.w;
            S[2][0] += qv.z * kv.x; S[2][1] += qv.z * kv.y; S[2][2] += qv.z * kv.z; S[2][3] += qv.z * kv.w;
            S[3][0] += qv.w * kv.x; S[3][1] += qv.w * kv.y; S[3][2] += qv.w * kv.z; S[3][3] += qv.w * kv.w;
        }

        // Online softmax update (row stats reduced over the 16 tx lanes)
#pragma unroll
        for (int i = 0; i < 4; i++) {
            float mt = fmaxf(fmaxf(S[i][0], S[i][1]), fmaxf(S[i][2], S[i][3]));
#pragma unroll
            for (int off = 8; off >= 1; off >>= 1)
                mt = fmaxf(mt, __shfl_xor_sync(0xffffffffu, mt, off));
            float mn = fmaxf(m[i], mt);
            float corr = __expf(m[i] - mn);
            float rs = 0.0f;
#pragma unroll
            for (int j = 0; j < 4; j++) {
                S[i][j] = __expf(S[i][j] - mn);
                rs += S[i][j];
            }
#pragma unroll
            for (int off = 8; off >= 1; off >>= 1)
                rs += __shfl_xor_sync(0xffffffffu, rs, off);
            l[i] = l[i] * corr + rs;
            m[i] = mn;
#pragma unroll
            for (int c = 0; c < 8; c++) O[i][c] *= corr;
            *(float4*)(Ps + (ty * 4 + i) * PITCH + tx * 4) =
                make_float4(S[i][0], S[i][1], S[i][2], S[i][3]);
        }
        __syncthreads();   // P written; K reads done -> reuse KVs for V

        // Load V tile row-major [64][128]
#pragma unroll
        for (int i = 0; i < 8; i++) {
            int f = tid + i * 256;
            ((float4*)KVs)[f] = ((const float4*)vb)[f];
        }
        __syncthreads();

        // O += P @ V
#pragma unroll 4
        for (int j = 0; j < 64; j++) {
            float4 v0 = *(const float4*)(KVs + j * 128 + tx * 8);
            float4 v1 = *(const float4*)(KVs + j * 128 + tx * 8 + 4);
#pragma unroll
            for (int i = 0; i < 4; i++) {
                float p = Ps[(ty * 4 + i) * PITCH + j];
                O[i][0] += p * v0.x; O[i][1] += p * v0.y;
                O[i][2] += p * v0.z; O[i][3] += p * v0.w;
                O[i][4] += p * v1.x; O[i][5] += p * v1.y;
                O[i][6] += p * v1.z; O[i][7] += p * v1.w;
            }
        }
    }

    // Normalize and write out
#pragma unroll
    for (int i = 0; i < 4; i++) {
        float inv = 1.0f / l[i];
        size_t row = (size_t)b * TT + qt * 64 + ty * 4 + i;
        *(float4*)(out + row * HH + tx * 8) =
            make_float4(O[i][0] * inv, O[i][1] * inv, O[i][2] * inv, O[i][3] * inv);
        *(float4*)(out + row * HH + tx * 8 + 4) =
            make_float4(O[i][4] * inv, O[i][5] * inv, O[i][6] * inv, O[i][7] * inv);
    }
}

// ---------------------------------------------------------------------------
extern "C" void kernel_launch(void* const* d_in, const int* in_sizes, int n_in,
                              void* d_out, int out_size) {
    const float* x  = (const float*)d_in[0];
    const float* Wk = (const float*)d_in[1];
    const float* Wq = (const float*)d_in[2];
    const float* Wv = (const float*)d_in[3];
    float* out = (float*)d_out;

    qkv_kernel<<<dim3((BB * TT) / 64, 3), 256>>>(x, Wq, Wk, Wv);

    cudaFuncSetAttribute(attn_kernel, cudaFuncAttributeMaxDynamicSharedMemorySize,
                         ATTN_SMEM_BYTES);
    attn_kernel<<<(BB * TT) / 64, 256, ATTN_SMEM_BYTES>>>(out);
}

// round 2
// speedup vs baseline: 4.2861x; 4.2861x over previous
#include <cuda_runtime.h>

#define BB 8
#define TT 2048
#define CC 1024
#define HH 128

// q,k,v scratch [B*T, H], values stored pre-rounded to tf32
__device__ float g_q[BB*TT*HH];
__device__ float g_k[BB*TT*HH];
__device__ float g_v[BB*TT*HH];

// -------------------------------------------------------------------------
// helpers
// -------------------------------------------------------------------------
__device__ __forceinline__ float to_tf32(float x) {
    unsigned u;
    asm("cvt.rna.tf32.f32 %0, %1;" : "=r"(u) : "f"(x));
    return __uint_as_float(u);
}

__device__ __forceinline__ void mma8(float* c, const unsigned* A, const unsigned* B) {
    asm volatile(
        "mma.sync.aligned.m16n8k8.row.col.f32.tf32.tf32.f32 "
        "{%0,%1,%2,%3}, {%4,%5,%6,%7}, {%8,%9}, {%0,%1,%2,%3};\n"
        : "+f"(c[0]), "+f"(c[1]), "+f"(c[2]), "+f"(c[3])
        : "r"(A[0]), "r"(A[1]), "r"(A[2]), "r"(A[3]), "r"(B[0]), "r"(B[1]));
}

__device__ __forceinline__ void cp16(unsigned dst, const void* src) {
    asm volatile("cp.async.cg.shared.global [%0], [%1], 16;" :: "r"(dst), "l"(src));
}
__device__ __forceinline__ void cp_commit() {
    asm volatile("cp.async.commit_group;");
}
__device__ __forceinline__ void cp_wait1() {
    asm volatile("cp.async.wait_group 1;");
}

// -------------------------------------------------------------------------
// Kernel 1: QKV projection with tf32 mma.
// grid=(128,3), block=256 (8 warps). Block tile 128(M)x128(N), K-tile 32.
// warp tile 32m x 64n (2 m-tiles x 8 n-tiles of m16n8k8).
// -------------------------------------------------------------------------
#define XP 36     // x smem pitch (mod 32 == 4 -> conflict-free A frags)
#define WP 136    // W smem pitch (mod 32 == 8 -> conflict-free B frags)

__global__ __launch_bounds__(256, 2) void qkv_mma(const float* __restrict__ x,
                                                  const float* __restrict__ Wq,
                                                  const float* __restrict__ Wk,
                                                  const float* __restrict__ Wv) {
    __shared__ float xs[128 * XP];
    __shared__ float ws[32 * WP];
    const unsigned* xu = (const unsigned*)xs;
    const unsigned* wu = (const unsigned*)ws;

    const int tid  = threadIdx.x;
    const int warp = tid >> 5;
    const int lane = tid & 31;
    const int g = lane >> 2;
    const int t = lane & 3;
    const int wm = warp >> 1;     // 0..3
    const int wn = warp & 1;      // 0..1

    const float* W;
    float* out;
    if (blockIdx.y == 0)      { W = Wq; out = g_q; }
    else if (blockIdx.y == 1) { W = Wk; out = g_k; }
    else                      { W = Wv; out = g_v; }

    const float* xb = x + (size_t)blockIdx.x * 128 * CC;

    float o[2][8][4];
#pragma unroll
    for (int mt = 0; mt < 2; mt++)
#pragma unroll
        for (int nt = 0; nt < 8; nt++)
#pragma unroll
            for (int e = 0; e < 4; e++) o[mt][nt][e] = 0.0f;

    for (int kt = 0; kt < 32; kt++) {
        const int k0 = kt * 32;
        // stage x tile [128][32] and W tile [32][128] through regs with rna cvt
        float4 xr[4], wr[4];
#pragma unroll
        for (int i = 0; i < 4; i++) {
            int f = tid + i * 256;
            int row = f >> 3, c4 = f & 7;
            xr[i] = *(const float4*)(xb + (size_t)row * CC + k0 + c4 * 4);
        }
#pragma unroll
        for (int i = 0; i < 4; i++) {
            int f = tid + i * 256;
            int row = f >> 5, c4 = f & 31;
            wr[i] = *(const float4*)(W + (size_t)(k0 + row) * HH + c4 * 4);
        }
        __syncthreads();
#pragma unroll
        for (int i = 0; i < 4; i++) {
            int f = tid + i * 256;
            int row = f >> 3, c4 = f & 7;
            float4 v = make_float4(to_tf32(xr[i].x), to_tf32(xr[i].y),
                                   to_tf32(xr[i].z), to_tf32(xr[i].w));
            *(float4*)(xs + row * XP + c4 * 4) = v;
        }
#pragma unroll
        for (int i = 0; i < 4; i++) {
            int f = tid + i * 256;
            int row = f >> 5, c4 = f & 31;
            float4 v = make_float4(to_tf32(wr[i].x), to_tf32(wr[i].y),
                                   to_tf32(wr[i].z), to_tf32(wr[i].w));
            *(float4*)(ws + row * WP + c4 * 4) = v;
        }
        __syncthreads();

#pragma unroll
        for (int ks = 0; ks < 4; ks++) {
            unsigned a[2][4];
#pragma unroll
            for (int mt = 0; mt < 2; mt++) {
                int r = wm * 32 + mt * 16;
                a[mt][0] = xu[(r + g) * XP + ks * 8 + t];
                a[mt][1] = xu[(r + g + 8) * XP + ks * 8 + t];
                a[mt][2] = xu[(r + g) * XP + ks * 8 + t + 4];
                a[mt][3] = xu[(r + g + 8) * XP + ks * 8 + t + 4];
            }
#pragma unroll
            for (int nt = 0; nt < 8; nt++) {
                int col = wn * 64 + nt * 8 + g;
                unsigned b[2];
                b[0] = wu[(ks * 8 + t) * WP + col];
                b[1] = wu[(ks * 8 + t + 4) * WP + col];
                mma8(o[0][nt], a[0], b);
                mma8(o[1][nt], a[1], b);
            }
        }
    }

    // epilogue: round to tf32 (attention consumes these exactly)
#pragma unroll
    for (int mt = 0; mt < 2; mt++)
#pragma unroll
        for (int nt = 0; nt < 8; nt++) {
            size_t r0 = (size_t)blockIdx.x * 128 + wm * 32 + mt * 16 + g;
            int c = wn * 64 + nt * 8 + 2 * t;
            float2 v0 = make_float2(to_tf32(o[mt][nt][0]), to_tf32(o[mt][nt][1]));
            float2 v1 = make_float2(to_tf32(o[mt][nt][2]), to_tf32(o[mt][nt][3]));
            *(float2*)(out + r0 * HH + c) = v0;
            *(float2*)(out + (r0 + 8) * HH + c) = v1;
        }
}

// -------------------------------------------------------------------------
// Kernel 2: flash attention with tf32 mma.
// grid=128 (BT/128), block=128 (4 warps, 32 q-rows each). 64 keys per iter.
// smem: Q[128][132], K double buf [64][132], V double buf [64][136]
// -------------------------------------------------------------------------
#define QP 132
#define KP 132
#define VP 136
#define Q_OFF 0
#define K_OFF (128 * QP)                 // 16896
#define KBUF  (64 * KP)                  // 8448
#define V_OFF (K_OFF + 2 * KBUF)         // 33792
#define VBUF  (64 * VP)                  // 8704
#define ATTN_SMEM ((V_OFF + 2 * VBUF) * 4)   // 204800 B

#define SCALE 0.04508422f  /* log2(e) / 32 */

__global__ __launch_bounds__(128, 1) void attn_mma(float* __restrict__ out) {
    extern __shared__ float sm[];
    const unsigned* smu = (const unsigned*)sm;
    unsigned sm_base = (unsigned)__cvta_generic_to_shared(sm);

    const int tid  = threadIdx.x;
    const int warp = tid >> 5;
    const int lane = tid & 31;
    const int g = lane >> 2;
    const int t = lane & 3;

    const int qrow0 = blockIdx.x * 128;           // global row in [0, B*T)
    const int batch = blockIdx.x >> 4;            // 16 q-blocks per batch
    const float* kb = g_k + (size_t)batch * TT * HH;
    const float* vb = g_v + (size_t)batch * TT * HH;
    const float* qb = g_q + (size_t)qrow0 * HH;

    // prefetch K0/V0 while staging Q
#pragma unroll
    for (int i = 0; i < 16; i++) {
        int f = tid + i * 128;
        int row = f >> 5, c4 = f & 31;
        cp16(sm_base + (K_OFF + row * KP + c4 * 4) * 4, kb + (size_t)row * HH + c4 * 4);
    }
#pragma unroll
    for (int i = 0; i < 16; i++) {
        int f = tid + i * 128;
        int row = f >> 5, c4 = f & 31;
        cp16(sm_base + (V_OFF + row * VP + c4 * 4) * 4, vb + (size_t)row * HH + c4 * 4);
    }
    cp_commit();

    // stage Q with scale (log2e/32) and rna rounding
#pragma unroll
    for (int i = 0; i < 32; i++) {
        int f = tid + i * 128;
        int row = f >> 5, c4 = f & 31;
        float4 v = *(const float4*)(qb + (size_t)row * HH + c4 * 4);
        float4 w = make_float4(to_tf32(v.x * SCALE), to_tf32(v.y * SCALE),
                               to_tf32(v.z * SCALE), to_tf32(v.w * SCALE));
        *(float4*)(sm + Q_OFF + row * QP + c4 * 4) = w;
    }

    float o[2][16][4];
    float m[2][2], l[2][2];
#pragma unroll
    for (int mt = 0; mt < 2; mt++) {
        m[mt][0] = -1e30f; m[mt][1] = -1e30f;
        l[mt][0] = 0.0f;   l[mt][1] = 0.0f;
#pragma unroll
        for (int nt = 0; nt < 16; nt++)
#pragma unroll
            for (int e = 0; e < 4; e++) o[mt][nt][e] = 0.0f;
    }

    const int qbase = warp * 32;   // warp's q-row offset within block

    for (int kt = 0; kt < 32; kt++) {
        __syncthreads();   // everyone done reading the buffer we're about to refill
        if (kt + 1 < 32) {
            int buf = (kt + 1) & 1;
            const float* kq = kb + (size_t)(kt + 1) * 64 * HH;
            const float* vq = vb + (size_t)(kt + 1) * 64 * HH;
#pragma unroll
            for (int i = 0; i < 16; i++) {
                int f = tid + i * 128;
                int row = f >> 5, c4 = f & 31;
                cp16(sm_base + (K_OFF + buf * KBUF + row * KP + c4 * 4) * 4,
                     kq + (size_t)row * HH + c4 * 4);
            }
#pragma unroll
            for (int i = 0; i < 16; i++) {
                int f = tid + i * 128;
                int row = f >> 5, c4 = f & 31;
                cp16(sm_base + (V_OFF + buf * VBUF + row * VP + c4 * 4) * 4,
                     vq + (size_t)row * HH + c4 * 4);
            }
        }
        cp_commit();
        cp_wait1();        // tile kt is resident
        __syncthreads();

        const unsigned* Ku = smu + K_OFF + (kt & 1) * KBUF;
        const unsigned* Vu = smu + V_OFF + (kt & 1) * VBUF;

        // ---- S = Q @ K^T (64 keys) ----
        float s[2][8][4];
#pragma unroll
        for (int mt = 0; mt < 2; mt++)
#pragma unroll
            for (int j = 0; j < 8; j++)
#pragma unroll
                for (int e = 0; e < 4; e++) s[mt][j][e] = 0.0f;

#pragma unroll 4
        for (int ks = 0; ks < 16; ks++) {
            unsigned a[2][4];
#pragma unroll
            for (int mt = 0; mt < 2; mt++) {
                int r = qbase + mt * 16;
                a[mt][0] = smu[Q_OFF + (r + g) * QP + ks * 8 + t];
                a[mt][1] = smu[Q_OFF + (r + g + 8) * QP + ks * 8 + t];
                a[mt][2] = smu[Q_OFF + (r + g) * QP + ks * 8 + t + 4];
                a[mt][3] = smu[Q_OFF + (r + g + 8) * QP + ks * 8 + t + 4];
            }
#pragma unroll
            for (int j = 0; j < 8; j++) {
                unsigned b[2];
                b[0] = Ku[(j * 8 + g) * KP + ks * 8 + t];
                b[1] = Ku[(j * 8 + g) * KP + ks * 8 + t + 4];
                mma8(s[0][j], a[0], b);
                mma8(s[1][j], a[1], b);
            }
        }

        // ---- online softmax (log2 domain) ----
#pragma unroll
        for (int mt = 0; mt < 2; mt++) {
            float mx0 = -1e30f, mx1 = -1e30f;
#pragma unroll
            for (int j = 0; j < 8; j++) {
                mx0 = fmaxf(mx0, fmaxf(s[mt][j][0], s[mt][j][1]));
                mx1 = fmaxf(mx1, fmaxf(s[mt][j][2], s[mt][j][3]));
            }
#pragma unroll
            for (int off = 1; off <= 2; off <<= 1) {
                mx0 = fmaxf(mx0, __shfl_xor_sync(0xffffffffu, mx0, off));
                mx1 = fmaxf(mx1, __shfl_xor_sync(0xffffffffu, mx1, off));
            }
            float mn0 = fmaxf(m[mt][0], mx0);
            float mn1 = fmaxf(m[mt][1], mx1);
            float c0 = exp2f(m[mt][0] - mn0);
            float c1 = exp2f(m[mt][1] - mn1);
            m[mt][0] = mn0; m[mt][1] = mn1;
            float s0 = 0.0f, s1 = 0.0f;
#pragma unroll
            for (int j = 0; j < 8; j++) {
                float p0 = exp2f(s[mt][j][0] - mn0);
                float p1 = exp2f(s[mt][j][1] - mn0);
                float p2 = exp2f(s[mt][j][2] - mn1);
                float p3 = exp2f(s[mt][j][3] - mn1);
                s0 += p0 + p1; s1 += p2 + p3;
                s[mt][j][0] = to_tf32(p0); s[mt][j][1] = to_tf32(p1);
                s[mt][j][2] = to_tf32(p2); s[mt][j][3] = to_tf32(p3);
            }
#pragma unroll
            for (int off = 1; off <= 2; off <<= 1) {
                s0 += __shfl_xor_sync(0xffffffffu, s0, off);
                s1 += __shfl_xor_sync(0xffffffffu, s1, off);
            }
            l[mt][0] = l[mt][0] * c0 + s0;
            l[mt][1] = l[mt][1] * c1 + s1;
#pragma unroll
            for (int nt = 0; nt < 16; nt++) {
                o[mt][nt][0] *= c0; o[mt][nt][1] *= c0;
                o[mt][nt][2] *= c1; o[mt][nt][3] *= c1;
            }
        }

        // ---- O += P @ V ----
        const int srcA = (lane & ~3) | (t >> 1);
        const int srcB = srcA + 2;
        const bool odd = (t & 1);
#pragma unroll
        for (int j = 0; j < 8; j++) {
            unsigned pa[2][4];
#pragma unroll
            for (int mt = 0; mt < 2; mt++) {
                float u0 = __shfl_sync(0xffffffffu, s[mt][j][0], srcA);
                float u1 = __shfl_sync(0xffffffffu, s[mt][j][1], srcA);
                float w0 = __shfl_sync(0xffffffffu, s[mt][j][0], srcB);
                float w1 = __shfl_sync(0xffffffffu, s[mt][j][1], srcB);
                float v0 = __shfl_sync(0xffffffffu, s[mt][j][2], srcA);
                float v1 = __shfl_sync(0xffffffffu, s[mt][j][3], srcA);
                float x0 = __shfl_sync(0xffffffffu, s[mt][j][2], srcB);
                float x1 = __shfl_sync(0xffffffffu, s[mt][j][3], srcB);
                pa[mt][0] = __float_as_uint(odd ? u1 : u0);
                pa[mt][1] = __float_as_uint(odd ? v1 : v0);
                pa[mt][2] = __float_as_uint(odd ? w1 : w0);
                pa[mt][3] = __float_as_uint(odd ? x1 : x0);
            }
#pragma unroll
            for (int nt = 0; nt < 16; nt++) {
                unsigned b[2];
                b[0] = Vu[(j * 8 + t) * VP + nt * 8 + g];
                b[1] = Vu[(j * 8 + t + 4) * VP + nt * 8 + g];
                mma8(o[0][nt], pa[0], b);
                mma8(o[1][nt], pa[1], b);
            }
        }
    }

    // ---- epilogue ----
#pragma unroll
    for (int mt = 0; mt < 2; mt++) {
        float inv0 = 1.0f / l[mt][0];
        float inv1 = 1.0f / l[mt][1];
        size_t r0 = (size_t)qrow0 + qbase + mt * 16 + g;
#pragma unroll
        for (int nt = 0; nt < 16; nt++) {
            int c = nt * 8 + 2 * t;
            *(float2*)(out + r0 * HH + c) =
                make_float2(o[mt][nt][0] * inv0, o[mt][nt][1] * inv0);
            *(float2*)(out + (r0 + 8) * HH + c) =
                make_float2(o[mt][nt][2] * inv1, o[mt][nt][3] * inv1);
        }
    }
}

// -------------------------------------------------------------------------
extern "C" void kernel_launch(void* const* d_in, const int* in_sizes, int n_in,
                              void* d_out, int out_size) {
    const float* x  = (const float*)d_in[0];
    const float* Wk = (const float*)d_in[1];
    const float* Wq = (const float*)d_in[2];
    const float* Wv = (const float*)d_in[3];
    float* out = (float*)d_out;

    qkv_mma<<<dim3(128, 3), 256>>>(x, Wq, Wk, Wv);

    cudaFuncSetAttribute(attn_mma, cudaFuncAttributeMaxDynamicSharedMemorySize,
                         ATTN_SMEM);
    attn_mma<<<128, 128, ATTN_SMEM>>>(out);
}

// round 3
// speedup vs baseline: 4.8202x; 1.1246x over previous
#include <cuda_runtime.h>

#define BB 8
#define TT 2048
#define CC 1024
#define HH 128

// q,k,v scratch [B*T, H], values stored pre-rounded to tf32
__device__ float g_q[BB*TT*HH];
__device__ float g_k[BB*TT*HH];
__device__ float g_v[BB*TT*HH];

// -------------------------------------------------------------------------
// helpers
// -------------------------------------------------------------------------
__device__ __forceinline__ float to_tf32(float x) {
    unsigned u;
    asm("cvt.rna.tf32.f32 %0, %1;" : "=r"(u) : "f"(x));
    return __uint_as_float(u);
}
__device__ __forceinline__ unsigned cvt_u(unsigned x) {
    unsigned u;
    asm("cvt.rna.tf32.f32 %0, %1;" : "=r"(u) : "f"(__uint_as_float(x)));
    return u;
}

__device__ __forceinline__ void mma8(float* c, const unsigned* A, const unsigned* B) {
    asm volatile(
        "mma.sync.aligned.m16n8k8.row.col.f32.tf32.tf32.f32 "
        "{%0,%1,%2,%3}, {%4,%5,%6,%7}, {%8,%9}, {%0,%1,%2,%3};\n"
        : "+f"(c[0]), "+f"(c[1]), "+f"(c[2]), "+f"(c[3])
        : "r"(A[0]), "r"(A[1]), "r"(A[2]), "r"(A[3]), "r"(B[0]), "r"(B[1]));
}

__device__ __forceinline__ void cp16(unsigned dst, const void* src) {
    asm volatile("cp.async.cg.shared.global [%0], [%1], 16;" :: "r"(dst), "l"(src));
}
__device__ __forceinline__ void cp_commit() {
    asm volatile("cp.async.commit_group;");
}
__device__ __forceinline__ void cp_wait1() {
    asm volatile("cp.async.wait_group 1;");
}

// -------------------------------------------------------------------------
// Kernel 1: QKV projection with tf32 mma + cp.async double buffering.
// grid=(128,3), block=256 (8 warps). Block tile 128(M)x128(N), K-tile 32.
// warp tile 32m x 64n. x/W staged raw; cvt.rna applied to fragments in regs.
// -------------------------------------------------------------------------
#define XP 36     // x smem pitch (mod 32 == 4 -> conflict-free A frags)
#define WP 136    // W smem pitch (mod 32 == 8 -> conflict-free B frags)
#define XBUF (128 * XP)
#define WBUF (32 * WP)
#define QKV_SMEM ((2 * XBUF + 2 * WBUF) * 4)   // 71680 B

__global__ __launch_bounds__(256, 2) void qkv_mma(const float* __restrict__ x,
                                                  const float* __restrict__ Wq,
                                                  const float* __restrict__ Wk,
                                                  const float* __restrict__ Wv) {
    extern __shared__ float sm[];
    float* xs = sm;                 // 2 x [128][36]
    float* ws = sm + 2 * XBUF;      // 2 x [32][136]
    unsigned sm_base = (unsigned)__cvta_generic_to_shared(sm);

    const int tid  = threadIdx.x;
    const int warp = tid >> 5;
    const int lane = tid & 31;
    const int g = lane >> 2;
    const int t = lane & 3;
    const int wm = warp >> 1;     // 0..3
    const int wn = warp & 1;      // 0..1

    const float* W;
    float* out;
    if (blockIdx.y == 0)      { W = Wq; out = g_q; }
    else if (blockIdx.y == 1) { W = Wk; out = g_k; }
    else                      { W = Wv; out = g_v; }

    const float* xb = x + (size_t)blockIdx.x * 128 * CC;

    // load x tile [128][32] at k0 into buffer buf
    auto issue_x = [&](int buf, int k0) {
#pragma unroll
        for (int i = 0; i < 4; i++) {
            int f = tid + i * 256;            // 0..1023 float4
            int row = f >> 3, c4 = f & 7;
            cp16(sm_base + (buf * XBUF + row * XP + c4 * 4) * 4,
                 xb + (size_t)row * CC + k0 + c4 * 4);
        }
    };
    // load W tile [32][128] at k0 into buffer buf
    auto issue_w = [&](int buf, int k0) {
#pragma unroll
        for (int i = 0; i < 4; i++) {
            int f = tid + i * 256;            // 0..1023 float4
            int row = f >> 5, c4 = f & 31;
            cp16(sm_base + (2 * XBUF + buf * WBUF + row * WP + c4 * 4) * 4,
                 W + (size_t)(k0 + row) * HH + c4 * 4);
        }
    };

    float o[2][8][4];
#pragma unroll
    for (int mt = 0; mt < 2; mt++)
#pragma unroll
        for (int nt = 0; nt < 8; nt++)
#pragma unroll
            for (int e = 0; e < 4; e++) o[mt][nt][e] = 0.0f;

    issue_x(0, 0);
    issue_w(0, 0);
    cp_commit();

    for (int kt = 0; kt < 32; kt++) {
        __syncthreads();   // readers of the buffer we are about to refill are done
        if (kt + 1 < 32) {
            issue_x((kt + 1) & 1, (kt + 1) * 32);
            issue_w((kt + 1) & 1, (kt + 1) * 32);
        }
        cp_commit();
        cp_wait1();        // tile kt resident
        __syncthreads();

        const unsigned* xu = (const unsigned*)(xs + (kt & 1) * XBUF);
        const unsigned* wu = (const unsigned*)(ws + 2 * 0 + (kt & 1) * WBUF);

#pragma unroll
        for (int ks = 0; ks < 4; ks++) {
            unsigned a[2][4];
#pragma unroll
            for (int mt = 0; mt < 2; mt++) {
                int r = wm * 32 + mt * 16;
                a[mt][0] = cvt_u(xu[(r + g) * XP + ks * 8 + t]);
                a[mt][1] = cvt_u(xu[(r + g + 8) * XP + ks * 8 + t]);
                a[mt][2] = cvt_u(xu[(r + g) * XP + ks * 8 + t + 4]);
                a[mt][3] = cvt_u(xu[(r + g + 8) * XP + ks * 8 + t + 4]);
            }
#pragma unroll
            for (int nt = 0; nt < 8; nt++) {
                int col = wn * 64 + nt * 8 + g;
                unsigned b[2];
                b[0] = cvt_u(wu[(ks * 8 + t) * WP + col]);
                b[1] = cvt_u(wu[(ks * 8 + t + 4) * WP + col]);
                mma8(o[0][nt], a[0], b);
                mma8(o[1][nt], a[1], b);
            }
        }
    }

    // epilogue: round to tf32 (attention consumes these exactly)
#pragma unroll
    for (int mt = 0; mt < 2; mt++)
#pragma unroll
        for (int nt = 0; nt < 8; nt++) {
            size_t r0 = (size_t)blockIdx.x * 128 + wm * 32 + mt * 16 + g;
            int c = wn * 64 + nt * 8 + 2 * t;
            float2 v0 = make_float2(to_tf32(o[mt][nt][0]), to_tf32(o[mt][nt][1]));
            float2 v1 = make_float2(to_tf32(o[mt][nt][2]), to_tf32(o[mt][nt][3]));
            *(float2*)(out + r0 * HH + c) = v0;
            *(float2*)(out + (r0 + 8) * HH + c) = v1;
        }
}

// -------------------------------------------------------------------------
// Kernel 2: flash attention with tf32 mma.
// grid=128 (BT/128), block=256 (8 warps, 16 q-rows each). 64 keys per iter.
// smem: Q[128][132], K double buf [64][132], V double buf [64][136]
// -------------------------------------------------------------------------
#define QP 132
#define KP 132
#define VP 136
#define Q_OFF 0
#define K_OFF (128 * QP)
#define KBUF  (64 * KP)
#define V_OFF (K_OFF + 2 * KBUF)
#define VBUF  (64 * VP)
#define ATTN_SMEM ((V_OFF + 2 * VBUF) * 4)   // 204800 B

#define SCALE 0.04508422f  /* log2(e) / 32 */

__global__ __launch_bounds__(256, 1) void attn_mma(float* __restrict__ out) {
    extern __shared__ float sm[];
    const unsigned* smu = (const unsigned*)sm;
    unsigned sm_base = (unsigned)__cvta_generic_to_shared(sm);

    const int tid  = threadIdx.x;
    const int warp = tid >> 5;
    const int lane = tid & 31;
    const int g = lane >> 2;
    const int t = lane & 3;

    const int qrow0 = blockIdx.x * 128;
    const int batch = blockIdx.x >> 4;
    const float* kb = g_k + (size_t)batch * TT * HH;
    const float* vb = g_v + (size_t)batch * TT * HH;
    const float* qb = g_q + (size_t)qrow0 * HH;

    // prefetch K0/V0 while staging Q
#pragma unroll
    for (int i = 0; i < 8; i++) {
        int f = tid + i * 256;
        int row = f >> 5, c4 = f & 31;
        cp16(sm_base + (K_OFF + row * KP + c4 * 4) * 4, kb + (size_t)row * HH + c4 * 4);
    }
#pragma unroll
    for (int i = 0; i < 8; i++) {
        int f = tid + i * 256;
        int row = f >> 5, c4 = f & 31;
        cp16(sm_base + (V_OFF + row * VP + c4 * 4) * 4, vb + (size_t)row * HH + c4 * 4);
    }
    cp_commit();

    // stage Q with scale (log2e/32) and rna rounding
#pragma unroll
    for (int i = 0; i < 16; i++) {
        int f = tid + i * 256;
        int row = f >> 5, c4 = f & 31;
        float4 v = *(const float4*)(qb + (size_t)row * HH + c4 * 4);
        float4 w = make_float4(to_tf32(v.x * SCALE), to_tf32(v.y * SCALE),
                               to_tf32(v.z * SCALE), to_tf32(v.w * SCALE));
        *(float4*)(sm + Q_OFF + row * QP + c4 * 4) = w;
    }

    float o[16][4];
    float m[2], l[2];
    m[0] = -1e30f; m[1] = -1e30f;
    l[0] = 0.0f;   l[1] = 0.0f;
#pragma unroll
    for (int nt = 0; nt < 16; nt++)
#pragma unroll
        for (int e = 0; e < 4; e++) o[nt][e] = 0.0f;

    const int qbase = warp * 16;   // warp's q-row offset within block

    for (int kt = 0; kt < 32; kt++) {
        __syncthreads();
        if (kt + 1 < 32) {
            int buf = (kt + 1) & 1;
            const float* kq = kb + (size_t)(kt + 1) * 64 * HH;
            const float* vq = vb + (size_t)(kt + 1) * 64 * HH;
#pragma unroll
            for (int i = 0; i < 8; i++) {
                int f = tid + i * 256;
                int row = f >> 5, c4 = f & 31;
                cp16(sm_base + (K_OFF + buf * KBUF + row * KP + c4 * 4) * 4,
                     kq + (size_t)row * HH + c4 * 4);
            }
#pragma unroll
            for (int i = 0; i < 8; i++) {
                int f = tid + i * 256;
                int row = f >> 5, c4 = f & 31;
                cp16(sm_base + (V_OFF + buf * VBUF + row * VP + c4 * 4) * 4,
                     vq + (size_t)row * HH + c4 * 4);
            }
        }
        cp_commit();
        cp_wait1();
        __syncthreads();

        const unsigned* Ku = smu + K_OFF + (kt & 1) * KBUF;
        const unsigned* Vu = smu + V_OFF + (kt & 1) * VBUF;

        // ---- S = Q @ K^T (16 rows x 64 keys per warp) ----
        float s[8][4];
#pragma unroll
        for (int j = 0; j < 8; j++)
#pragma unroll
            for (int e = 0; e < 4; e++) s[j][e] = 0.0f;

#pragma unroll 4
        for (int ks = 0; ks < 16; ks++) {
            unsigned a[4];
            a[0] = smu[Q_OFF + (qbase + g) * QP + ks * 8 + t];
            a[1] = smu[Q_OFF + (qbase + g + 8) * QP + ks * 8 + t];
            a[2] = smu[Q_OFF + (qbase + g) * QP + ks * 8 + t + 4];
            a[3] = smu[Q_OFF + (qbase + g + 8) * QP + ks * 8 + t + 4];
#pragma unroll
            for (int j = 0; j < 8; j++) {
                unsigned b[2];
                b[0] = Ku[(j * 8 + g) * KP + ks * 8 + t];
                b[1] = Ku[(j * 8 + g) * KP + ks * 8 + t + 4];
                mma8(s[j], a, b);
            }
        }

        // ---- online softmax (log2 domain) ----
        {
            float mx0 = -1e30f, mx1 = -1e30f;
#pragma unroll
            for (int j = 0; j < 8; j++) {
                mx0 = fmaxf(mx0, fmaxf(s[j][0], s[j][1]));
                mx1 = fmaxf(mx1, fmaxf(s[j][2], s[j][3]));
            }
#pragma unroll
            for (int off = 1; off <= 2; off <<= 1) {
                mx0 = fmaxf(mx0, __shfl_xor_sync(0xffffffffu, mx0, off));
                mx1 = fmaxf(mx1, __shfl_xor_sync(0xffffffffu, mx1, off));
            }
            float mn0 = fmaxf(m[0], mx0);
            float mn1 = fmaxf(m[1], mx1);
            float c0 = exp2f(m[0] - mn0);
            float c1 = exp2f(m[1] - mn1);
            m[0] = mn0; m[1] = mn1;
            float s0 = 0.0f, s1 = 0.0f;
#pragma unroll
            for (int j = 0; j < 8; j++) {
                float p0 = exp2f(s[j][0] - mn0);
                float p1 = exp2f(s[j][1] - mn0);
                float p2 = exp2f(s[j][2] - mn1);
                float p3 = exp2f(s[j][3] - mn1);
                s0 += p0 + p1; s1 += p2 + p3;
                s[j][0] = to_tf32(p0); s[j][1] = to_tf32(p1);
                s[j][2] = to_tf32(p2); s[j][3] = to_tf32(p3);
            }
#pragma unroll
            for (int off = 1; off <= 2; off <<= 1) {
                s0 += __shfl_xor_sync(0xffffffffu, s0, off);
                s1 += __shfl_xor_sync(0xffffffffu, s1, off);
            }
            l[0] = l[0] * c0 + s0;
            l[1] = l[1] * c1 + s1;
#pragma unroll
            for (int nt = 0; nt < 16; nt++) {
                o[nt][0] *= c0; o[nt][1] *= c0;
                o[nt][2] *= c1; o[nt][3] *= c1;
            }
        }

        // ---- O += P @ V (C-frag -> A-frag via quad shuffles) ----
        const int srcA = (lane & ~3) | (t >> 1);
        const int srcB = srcA + 2;
        const bool odd = (t & 1);
#pragma unroll
        for (int j = 0; j < 8; j++) {
            unsigned pa[4];
            {
                float u0 = __shfl_sync(0xffffffffu, s[j][0], srcA);
                float u1 = __shfl_sync(0xffffffffu, s[j][1], srcA);
                float w0 = __shfl_sync(0xffffffffu, s[j][0], srcB);
                float w1 = __shfl_sync(0xffffffffu, s[j][1], srcB);
                float v0 = __shfl_sync(0xffffffffu, s[j][2], srcA);
                float v1 = __shfl_sync(0xffffffffu, s[j][3], srcA);
                float x0 = __shfl_sync(0xffffffffu, s[j][2], srcB);
                float x1 = __shfl_sync(0xffffffffu, s[j][3], srcB);
                pa[0] = __float_as_uint(odd ? u1 : u0);
                pa[1] = __float_as_uint(odd ? v1 : v0);
                pa[2] = __float_as_uint(odd ? w1 : w0);
                pa[3] = __float_as_uint(odd ? x1 : x0);
            }
#pragma unroll
            for (int nt = 0; nt < 16; nt++) {
                unsigned b[2];
                b[0] = Vu[(j * 8 + t) * VP + nt * 8 + g];
                b[1] = Vu[(j * 8 + t + 4) * VP + nt * 8 + g];
                mma8(o[nt], pa, b);
            }
        }
    }

    // ---- epilogue ----
    {
        float inv0 = 1.0f / l[0];
        float inv1 = 1.0f / l[1];
        size_t r0 = (size_t)qrow0 + qbase + g;
#pragma unroll
        for (int nt = 0; nt < 16; nt++) {
            int c = nt * 8 + 2 * t;
            *(float2*)(out + r0 * HH + c) =
                make_float2(o[nt][0] * inv0, o[nt][1] * inv0);
            *(float2*)(out + (r0 + 8) * HH + c) =
                make_float2(o[nt][2] * inv1, o[nt][3] * inv1);
        }
    }
}

// -------------------------------------------------------------------------
extern "C" void kernel_launch(void* const* d_in, const int* in_sizes, int n_in,
                              void* d_out, int out_size) {
    const float* x  = (const float*)d_in[0];
    const float* Wk = (const float*)d_in[1];
    const float* Wq = (const float*)d_in[2];
    const float* Wv = (const float*)d_in[3];
    float* out = (float*)d_out;

    cudaFuncSetAttribute(qkv_mma, cudaFuncAttributeMaxDynamicSharedMemorySize,
                         QKV_SMEM);
    qkv_mma<<<dim3(128, 3), 256, QKV_SMEM>>>(x, Wq, Wk, Wv);

    cudaFuncSetAttribute(attn_mma, cudaFuncAttributeMaxDynamicSharedMemorySize,
                         ATTN_SMEM);
    attn_mma<<<128, 256, ATTN_SMEM>>>(out);
}

// round 5
// speedup vs baseline: 4.9232x; 1.0214x over previous
#include <cuda_runtime.h>

#define BB 8
#define TT 2048
#define CC 1024
#define HH 128

// q,k,v scratch [B*T, H] row-major, values pre-rounded to tf32
__device__ float g_q[BB*TT*HH];
__device__ float g_k[BB*TT*HH];
__device__ float g_v[BB*TT*HH];
// W packed B-fragments [proj(3)][kt(32)][nchunk(16)][ksp(2)][lane(32)][4 floats]
__device__ float g_w[3*CC*HH];

// -------------------------------------------------------------------------
__device__ __forceinline__ float to_tf32(float x) {
    unsigned u;
    asm("cvt.rna.tf32.f32 %0, %1;" : "=r"(u) : "f"(x));
    return __uint_as_float(u);
}
__device__ __forceinline__ unsigned cvt_u(unsigned x) {
    unsigned u;
    asm("cvt.rna.tf32.f32 %0, %1;" : "=r"(u) : "f"(__uint_as_float(x)));
    return u;
}
__device__ __forceinline__ void mma8(float* c, const unsigned* A, const unsigned* B) {
    asm volatile(
        "mma.sync.aligned.m16n8k8.row.col.f32.tf32.tf32.f32 "
        "{%0,%1,%2,%3}, {%4,%5,%6,%7}, {%8,%9}, {%0,%1,%2,%3};\n"
        : "+f"(c[0]), "+f"(c[1]), "+f"(c[2]), "+f"(c[3])
        : "r"(A[0]), "r"(A[1]), "r"(A[2]), "r"(A[3]), "r"(B[0]), "r"(B[1]));
}
__device__ __forceinline__ void cp16(unsigned dst, const void* src) {
    asm volatile("cp.async.cg.shared.global [%0], [%1], 16;" :: "r"(dst), "l"(src));
}
__device__ __forceinline__ void cp_commit() { asm volatile("cp.async.commit_group;"); }
__device__ __forceinline__ void cp_wait1()  { asm volatile("cp.async.wait_group 1;"); }

// -------------------------------------------------------------------------
// Prepass: round W to tf32 and pack into B-fragment layout.
// One thread per output float4, total 3*32*16*2*32 = 98304.
// frag (lane g,t): {W[ke+t][col], W[ke+t+4][col], W[ke+8+t][col], W[ke+8+t+4][col]}
// with ke = kt*32 + ksp*16, col = nchunk*8 + g.
// -------------------------------------------------------------------------
__global__ void pack_w(const float* __restrict__ W0, const float* __restrict__ W1,
                       const float* __restrict__ W2) {
    int f = blockIdx.x * 256 + threadIdx.x;
    int lane = f & 31;
    int ksp  = (f >> 5) & 1;
    int nchunk = (f >> 6) & 15;
    int kt = (f >> 10) & 31;
    int y  = f >> 15;
    const float* W = (y == 0) ? W0 : (y == 1) ? W1 : W2;
    int g = lane >> 2, t = lane & 3;
    int ke = kt * 32 + ksp * 16;
    int col = nchunk * 8 + g;
    float4 o;
    o.x = to_tf32(W[(size_t)(ke + t)     * HH + col]);
    o.y = to_tf32(W[(size_t)(ke + t + 4) * HH + col]);
    o.z = to_tf32(W[(size_t)(ke + 8 + t)     * HH + col]);
    o.w = to_tf32(W[(size_t)(ke + 8 + t + 4) * HH + col]);
    *(float4*)(g_w + (size_t)f * 4) = o;
}

// -------------------------------------------------------------------------
// Kernel 1: QKV projection. grid=(3,128): x=proj (adjacent -> x L2 reuse),
// y=row-block. block 256 (8 warps), tile 128x128, warp 32x64.
// W consumed pre-packed (vector LDS, no cvt); x staged raw + cvt in regs.
// Epilogue: plain row-major tf32 stores (round-3 layout).
// -------------------------------------------------------------------------
#define XP 36
#define XBUF (128 * XP)          // floats
#define WTILE 4096               // floats per kt (16 nchunk * 2 ksp * 32 lanes * 4)
#define QKV_SMEM ((2 * XBUF + 2 * WTILE) * 4)   // 69632 B

__global__ __launch_bounds__(256, 2) void qkv_mma(const float* __restrict__ x) {
    extern __shared__ float sm[];
    float* xs = sm;                       // 2 x [128][36] raw f32
    float* ws = sm + 2 * XBUF;            // 2 x packed W tile
    unsigned sm_base = (unsigned)__cvta_generic_to_shared(sm);

    const int tid  = threadIdx.x;
    const int warp = tid >> 5;
    const int lane = tid & 31;
    const int g = lane >> 2;
    const int t = lane & 3;
    const int wm = warp >> 1;       // 0..3 : rows wm*32
    const int wn = warp & 1;        // 0..1 : cols wn*64
    const int proj = blockIdx.x;    // 0=q 1=k 2=v
    const int rb   = blockIdx.y;

    float* out = (proj == 0) ? g_q : (proj == 1) ? g_k : g_v;
    const float* xb = x + (size_t)rb * 128 * CC;
    const float* wb = g_w + (size_t)proj * 32 * WTILE;

    auto issue_x = [&](int buf, int k0) {
#pragma unroll
        for (int i = 0; i < 4; i++) {
            int f = tid + i * 256;           // 1024 float4
            int row = f >> 3, c4 = f & 7;
            cp16(sm_base + (buf * XBUF + row * XP + c4 * 4) * 4,
                 xb + (size_t)row * CC + k0 + c4 * 4);
        }
    };
    auto issue_w = [&](int buf, int kt) {
#pragma unroll
        for (int i = 0; i < 4; i++) {
            int f = tid + i * 256;           // 1024 float4
            cp16(sm_base + (2 * XBUF + buf * WTILE + f * 4) * 4,
                 wb + (size_t)kt * WTILE + f * 4);
        }
    };

    float o[2][8][4];
#pragma unroll
    for (int mt = 0; mt < 2; mt++)
#pragma unroll
        for (int nt = 0; nt < 8; nt++)
#pragma unroll
            for (int e = 0; e < 4; e++) o[mt][nt][e] = 0.0f;

    issue_x(0, 0);
    issue_w(0, 0);
    cp_commit();

    for (int kt = 0; kt < 32; kt++) {
        __syncthreads();
        if (kt + 1 < 32) { issue_x((kt + 1) & 1, (kt + 1) * 32); issue_w((kt + 1) & 1, kt + 1); }
        cp_commit();
        cp_wait1();
        __syncthreads();

        const unsigned* xu = (const unsigned*)(xs + (kt & 1) * XBUF);
        const float4*   w4 = (const float4*)(ws + (kt & 1) * WTILE);

#pragma unroll
        for (int ksp = 0; ksp < 2; ksp++) {
            unsigned aE[2][4], aO[2][4];
#pragma unroll
            for (int mt = 0; mt < 2; mt++) {
                int r = wm * 32 + mt * 16;
                int cb = ksp * 16;
                aE[mt][0] = cvt_u(xu[(r + g)     * XP + cb + t]);
                aE[mt][1] = cvt_u(xu[(r + g + 8) * XP + cb + t]);
                aE[mt][2] = cvt_u(xu[(r + g)     * XP + cb + t + 4]);
                aE[mt][3] = cvt_u(xu[(r + g + 8) * XP + cb + t + 4]);
                aO[mt][0] = cvt_u(xu[(r + g)     * XP + cb + 8 + t]);
                aO[mt][1] = cvt_u(xu[(r + g + 8) * XP + cb + 8 + t]);
                aO[mt][2] = cvt_u(xu[(r + g)     * XP + cb + 8 + t + 4]);
                aO[mt][3] = cvt_u(xu[(r + g + 8) * XP + cb + 8 + t + 4]);
            }
#pragma unroll
            for (int nt = 0; nt < 8; nt++) {
                int nchunk = wn * 8 + nt;
                float4 bb = w4[(nchunk * 2 + ksp) * 32 + lane];
                mma8(o[0][nt], aE[0], (const unsigned*)&bb.x);
                mma8(o[0][nt], aO[0], (const unsigned*)&bb.z);
                mma8(o[1][nt], aE[1], (const unsigned*)&bb.x);
                mma8(o[1][nt], aO[1], (const unsigned*)&bb.z);
            }
        }
    }

    // ---- epilogue: row-major tf32 stores (round-3 layout) ----
#pragma unroll
    for (int mt = 0; mt < 2; mt++)
#pragma unroll
        for (int nt = 0; nt < 8; nt++) {
            size_t r0 = (size_t)rb * 128 + wm * 32 + mt * 16 + g;
            int c = wn * 64 + nt * 8 + 2 * t;
            float2 v0 = make_float2(to_tf32(o[mt][nt][0]), to_tf32(o[mt][nt][1]));
            float2 v1 = make_float2(to_tf32(o[mt][nt][2]), to_tf32(o[mt][nt][3]));
            *(float2*)(out + r0 * HH + c) = v0;
            *(float2*)(out + (r0 + 8) * HH + c) = v1;
        }
}

// -------------------------------------------------------------------------
// Kernel 2: flash attention with tf32 mma (round-3 verbatim, known good).
// grid=128 (BT/128), block=256 (8 warps, 16 q-rows each). 64 keys per iter.
// smem: Q[128][132], K double buf [64][132], V double buf [64][136]
// -------------------------------------------------------------------------
#define QP 132
#define KP 132
#define VP 136
#define Q_OFF 0
#define K_OFF (128 * QP)
#define KBUF  (64 * KP)
#define V_OFF (K_OFF + 2 * KBUF)
#define VBUF  (64 * VP)
#define ATTN_SMEM ((V_OFF + 2 * VBUF) * 4)   // 204800 B

#define SCALE 0.04508422f  /* log2(e) / 32 */

__global__ __launch_bounds__(256, 1) void attn_mma(float* __restrict__ out) {
    extern __shared__ float sm[];
    const unsigned* smu = (const unsigned*)sm;
    unsigned sm_base = (unsigned)__cvta_generic_to_shared(sm);

    const int tid  = threadIdx.x;
    const int warp = tid >> 5;
    const int lane = tid & 31;
    const int g = lane >> 2;
    const int t = lane & 3;

    const int qrow0 = blockIdx.x * 128;
    const int batch = blockIdx.x >> 4;
    const float* kb = g_k + (size_t)batch * TT * HH;
    const float* vb = g_v + (size_t)batch * TT * HH;
    const float* qb = g_q + (size_t)qrow0 * HH;

    // prefetch K0/V0 while staging Q
#pragma unroll
    for (int i = 0; i < 8; i++) {
        int f = tid + i * 256;
        int row = f >> 5, c4 = f & 31;
        cp16(sm_base + (K_OFF + row * KP + c4 * 4) * 4, kb + (size_t)row * HH + c4 * 4);
    }
#pragma unroll
    for (int i = 0; i < 8; i++) {
        int f = tid + i * 256;
        int row = f >> 5, c4 = f & 31;
        cp16(sm_base + (V_OFF + row * VP + c4 * 4) * 4, vb + (size_t)row * HH + c4 * 4);
    }
    cp_commit();

    // stage Q with scale (log2e/32) and rna rounding
#pragma unroll
    for (int i = 0; i < 16; i++) {
        int f = tid + i * 256;
        int row = f >> 5, c4 = f & 31;
        float4 v = *(const float4*)(qb + (size_t)row * HH + c4 * 4);
        float4 w = make_float4(to_tf32(v.x * SCALE), to_tf32(v.y * SCALE),
                               to_tf32(v.z * SCALE), to_tf32(v.w * SCALE));
        *(float4*)(sm + Q_OFF + row * QP + c4 * 4) = w;
    }

    float o[16][4];
    float m[2] = {-1e30f, -1e30f}, l[2] = {0.0f, 0.0f};
#pragma unroll
    for (int nt = 0; nt < 16; nt++)
#pragma unroll
        for (int e = 0; e < 4; e++) o[nt][e] = 0.0f;

    const int qbase = warp * 16;

    for (int kt = 0; kt < 32; kt++) {
        __syncthreads();
        if (kt + 1 < 32) {
            int buf = (kt + 1) & 1;
            const float* kq = kb + (size_t)(kt + 1) * 64 * HH;
            const float* vq = vb + (size_t)(kt + 1) * 64 * HH;
#pragma unroll
            for (int i = 0; i < 8; i++) {
                int f = tid + i * 256;
                int row = f >> 5, c4 = f & 31;
                cp16(sm_base + (K_OFF + buf * KBUF + row * KP + c4 * 4) * 4,
                     kq + (size_t)row * HH + c4 * 4);
            }
#pragma unroll
            for (int i = 0; i < 8; i++) {
                int f = tid + i * 256;
                int row = f >> 5, c4 = f & 31;
                cp16(sm_base + (V_OFF + buf * VBUF + row * VP + c4 * 4) * 4,
                     vq + (size_t)row * HH + c4 * 4);
            }
        }
        cp_commit();
        cp_wait1();
        __syncthreads();

        const unsigned* Ku = smu + K_OFF + (kt & 1) * KBUF;
        const unsigned* Vu = smu + V_OFF + (kt & 1) * VBUF;

        // ---- S = Q @ K^T ----
        float s[8][4];
#pragma unroll
        for (int j = 0; j < 8; j++)
#pragma unroll
            for (int e = 0; e < 4; e++) s[j][e] = 0.0f;

#pragma unroll 4
        for (int ks = 0; ks < 16; ks++) {
            unsigned a[4];
            a[0] = smu[Q_OFF + (qbase + g) * QP + ks * 8 + t];
            a[1] = smu[Q_OFF + (qbase + g + 8) * QP + ks * 8 + t];
            a[2] = smu[Q_OFF + (qbase + g) * QP + ks * 8 + t + 4];
            a[3] = smu[Q_OFF + (qbase + g + 8) * QP + ks * 8 + t + 4];
#pragma unroll
            for (int j = 0; j < 8; j++) {
                unsigned b[2];
                b[0] = Ku[(j * 8 + g) * KP + ks * 8 + t];
                b[1] = Ku[(j * 8 + g) * KP + ks * 8 + t + 4];
                mma8(s[j], a, b);
            }
        }

        // ---- online softmax (log2 domain) ----
        {
            float mx0 = -1e30f, mx1 = -1e30f;
#pragma unroll
            for (int j = 0; j < 8; j++) {
                mx0 = fmaxf(mx0, fmaxf(s[j][0], s[j][1]));
                mx1 = fmaxf(mx1, fmaxf(s[j][2], s[j][3]));
            }
#pragma unroll
            for (int off = 1; off <= 2; off <<= 1) {
                mx0 = fmaxf(mx0, __shfl_xor_sync(~0u, mx0, off));
                mx1 = fmaxf(mx1, __shfl_xor_sync(~0u, mx1, off));
            }
            float mn0 = fmaxf(m[0], mx0), mn1 = fmaxf(m[1], mx1);
            float c0 = exp2f(m[0] - mn0), c1 = exp2f(m[1] - mn1);
            m[0] = mn0; m[1] = mn1;
            float s0 = 0.0f, s1 = 0.0f;
#pragma unroll
            for (int j = 0; j < 8; j++) {
                float p0 = exp2f(s[j][0] - mn0);
                float p1 = exp2f(s[j][1] - mn0);
                float p2 = exp2f(s[j][2] - mn1);
                float p3 = exp2f(s[j][3] - mn1);
                s0 += p0 + p1; s1 += p2 + p3;
                s[j][0] = to_tf32(p0); s[j][1] = to_tf32(p1);
                s[j][2] = to_tf32(p2); s[j][3] = to_tf32(p3);
            }
#pragma unroll
            for (int off = 1; off <= 2; off <<= 1) {
                s0 += __shfl_xor_sync(~0u, s0, off);
                s1 += __shfl_xor_sync(~0u, s1, off);
            }
            l[0] = l[0] * c0 + s0;
            l[1] = l[1] * c1 + s1;
#pragma unroll
            for (int nt = 0; nt < 16; nt++) {
                o[nt][0] *= c0; o[nt][1] *= c0;
                o[nt][2] *= c1; o[nt][3] *= c1;
            }
        }

        // ---- O += P @ V (C-frag -> A-frag via quad shuffles) ----
        const int srcA = (lane & ~3) | (t >> 1);
        const int srcB = srcA + 2;
        const bool odd = (t & 1);
#pragma unroll
        for (int j = 0; j < 8; j++) {
            unsigned pa[4];
            {
                float u0 = __shfl_sync(~0u, s[j][0], srcA);
                float u1 = __shfl_sync(~0u, s[j][1], srcA);
                float w0 = __shfl_sync(~0u, s[j][0], srcB);
                float w1 = __shfl_sync(~0u, s[j][1], srcB);
                float v0 = __shfl_sync(~0u, s[j][2], srcA);
                float v1 = __shfl_sync(~0u, s[j][3], srcA);
                float x0 = __shfl_sync(~0u, s[j][2], srcB);
                float x1 = __shfl_sync(~0u, s[j][3], srcB);
                pa[0] = __float_as_uint(odd ? u1 : u0);
                pa[1] = __float_as_uint(odd ? v1 : v0);
                pa[2] = __float_as_uint(odd ? w1 : w0);
                pa[3] = __float_as_uint(odd ? x1 : x0);
            }
#pragma unroll
            for (int nt = 0; nt < 16; nt++) {
                unsigned b[2];
                b[0] = Vu[(j * 8 + t) * VP + nt * 8 + g];
                b[1] = Vu[(j * 8 + t + 4) * VP + nt * 8 + g];
                mma8(o[nt], pa, b);
            }
        }
    }

    // ---- epilogue ----
    {
        float inv0 = 1.0f / l[0];
        float inv1 = 1.0f / l[1];
        size_t r0 = (size_t)qrow0 + qbase + g;
#pragma unroll
        for (int nt = 0; nt < 16; nt++) {
            int c = nt * 8 + 2 * t;
            *(float2*)(out + r0 * HH + c) =
                make_float2(o[nt][0] * inv0, o[nt][1] * inv0);
            *(float2*)(out + (r0 + 8) * HH + c) =
                make_float2(o[nt][2] * inv1, o[nt][3] * inv1);
        }
    }
}

// -------------------------------------------------------------------------
extern "C" void kernel_launch(void* const* d_in, const int* in_sizes, int n_in,
                              void* d_out, int out_size) {
    const float* x  = (const float*)d_in[0];
    const float* Wk = (const float*)d_in[1];
    const float* Wq = (const float*)d_in[2];
    const float* Wv = (const float*)d_in[3];
    float* out = (float*)d_out;

    pack_w<<<384, 256>>>(Wq, Wk, Wv);

    cudaFuncSetAttribute(qkv_mma, cudaFuncAttributeMaxDynamicSharedMemorySize, QKV_SMEM);
    qkv_mma<<<dim3(3, 128), 256, QKV_SMEM>>>(x);

    cudaFuncSetAttribute(attn_mma, cudaFuncAttributeMaxDynamicSharedMemorySize, ATTN_SMEM);
    attn_mma<<<128, 256, ATTN_SMEM>>>(out);
}

// round 6
// speedup vs baseline: 5.4739x; 1.1119x over previous
#include <cuda_runtime.h>

#define BB 8
#define TT 2048
#define CC 1024
#define HH 128

#define SCALE 0.04508422f  /* log2(e) / 32 */

// q: packed A-fragments  [qblock(128)][mtile(8)][ksp(8)][lane(32)][8 floats]
// k: packed B-fragments  [batch(8)][ktile(32)][jg(8)][ksp(8)][lane(32)][4 floats]
// v: packed B-fragments  [batch(8)][ktile(32)][jg(8)][dp(8)][lane(32)][4 floats]
__device__ float g_q[BB*TT*HH];
__device__ float g_k[BB*TT*HH];
__device__ float g_v[BB*TT*HH];
// W packed B-fragments [proj(3)][kt(32)][nchunk(16)][ksp(2)][lane(32)][4 floats]
__device__ float g_w[3*CC*HH];

// -------------------------------------------------------------------------
__device__ __forceinline__ float to_tf32(float x) {
    unsigned u;
    asm("cvt.rna.tf32.f32 %0, %1;" : "=r"(u) : "f"(x));
    return __uint_as_float(u);
}
__device__ __forceinline__ unsigned cvt_u(unsigned x) {
    unsigned u;
    asm("cvt.rna.tf32.f32 %0, %1;" : "=r"(u) : "f"(__uint_as_float(x)));
    return u;
}
__device__ __forceinline__ void mma8(float* c, const unsigned* A, const unsigned* B) {
    asm volatile(
        "mma.sync.aligned.m16n8k8.row.col.f32.tf32.tf32.f32 "
        "{%0,%1,%2,%3}, {%4,%5,%6,%7}, {%8,%9}, {%0,%1,%2,%3};\n"
        : "+f"(c[0]), "+f"(c[1]), "+f"(c[2]), "+f"(c[3])
        : "r"(A[0]), "r"(A[1]), "r"(A[2]), "r"(A[3]), "r"(B[0]), "r"(B[1]));
}
__device__ __forceinline__ void cp16(unsigned dst, const void* src) {
    asm volatile("cp.async.cg.shared.global [%0], [%1], 16;" :: "r"(dst), "l"(src));
}
__device__ __forceinline__ void cp_commit() { asm volatile("cp.async.commit_group;"); }
__device__ __forceinline__ void cp_wait1()  { asm volatile("cp.async.wait_group 1;"); }

// -------------------------------------------------------------------------
// Prepass: round W to tf32 and pack into B-fragment layout.
// -------------------------------------------------------------------------
__global__ void pack_w(const float* __restrict__ W0, const float* __restrict__ W1,
                       const float* __restrict__ W2) {
    int f = blockIdx.x * 256 + threadIdx.x;
    int lane = f & 31;
    int ksp  = (f >> 5) & 1;
    int nchunk = (f >> 6) & 15;
    int kt = (f >> 10) & 31;
    int y  = f >> 15;
    const float* W = (y == 0) ? W0 : (y == 1) ? W1 : W2;
    int g = lane >> 2, t = lane & 3;
    int ke = kt * 32 + ksp * 16;
    int col = nchunk * 8 + g;
    float4 o;
    o.x = to_tf32(W[(size_t)(ke + t)     * HH + col]);
    o.y = to_tf32(W[(size_t)(ke + t + 4) * HH + col]);
    o.z = to_tf32(W[(size_t)(ke + 8 + t)     * HH + col]);
    o.w = to_tf32(W[(size_t)(ke + 8 + t + 4) * HH + col]);
    *(float4*)(g_w + (size_t)f * 4) = o;
}

// -------------------------------------------------------------------------
// Kernel 1: QKV projection. grid=(3,128). block 256, tile 128x128, warp 32x64.
// Epilogue converts C-frags into packed fragment layouts (shuffles HOISTED).
// -------------------------------------------------------------------------
#define XP 36
#define XBUF (128 * XP)
#define WTILE 4096
#define QKV_SMEM ((2 * XBUF + 2 * WTILE) * 4)   // 69632 B

__global__ __launch_bounds__(256, 2) void qkv_mma(const float* __restrict__ x) {
    extern __shared__ float sm[];
    float* xs = sm;
    float* ws = sm + 2 * XBUF;
    unsigned sm_base = (unsigned)__cvta_generic_to_shared(sm);

    const int tid  = threadIdx.x;
    const int warp = tid >> 5;
    const int lane = tid & 31;
    const int g = lane >> 2;
    const int t = lane & 3;
    const int wm = warp >> 1;
    const int wn = warp & 1;
    const int proj = blockIdx.x;    // 0=q 1=k 2=v
    const int rb   = blockIdx.y;

    const float* xb = x + (size_t)rb * 128 * CC;
    const float* wb = g_w + (size_t)proj * 32 * WTILE;

    auto issue_x = [&](int buf, int k0) {
#pragma unroll
        for (int i = 0; i < 4; i++) {
            int f = tid + i * 256;
            int row = f >> 3, c4 = f & 7;
            cp16(sm_base + (buf * XBUF + row * XP + c4 * 4) * 4,
                 xb + (size_t)row * CC + k0 + c4 * 4);
        }
    };
    auto issue_w = [&](int buf, int kt) {
#pragma unroll
        for (int i = 0; i < 4; i++) {
            int f = tid + i * 256;
            cp16(sm_base + (2 * XBUF + buf * WTILE + f * 4) * 4,
                 wb + (size_t)kt * WTILE + f * 4);
        }
    };

    float o[2][8][4];
#pragma unroll
    for (int mt = 0; mt < 2; mt++)
#pragma unroll
        for (int nt = 0; nt < 8; nt++)
#pragma unroll
            for (int e = 0; e < 4; e++) o[mt][nt][e] = 0.0f;

    issue_x(0, 0);
    issue_w(0, 0);
    cp_commit();

    for (int kt = 0; kt < 32; kt++) {
        __syncthreads();
        if (kt + 1 < 32) { issue_x((kt + 1) & 1, (kt + 1) * 32); issue_w((kt + 1) & 1, kt + 1); }
        cp_commit();
        cp_wait1();
        __syncthreads();

        const unsigned* xu = (const unsigned*)(xs + (kt & 1) * XBUF);
        const float4*   w4 = (const float4*)(ws + (kt & 1) * WTILE);

#pragma unroll
        for (int ksp = 0; ksp < 2; ksp++) {
            unsigned aE[2][4], aO[2][4];
#pragma unroll
            for (int mt = 0; mt < 2; mt++) {
                int r = wm * 32 + mt * 16;
                int cb = ksp * 16;
                aE[mt][0] = cvt_u(xu[(r + g)     * XP + cb + t]);
                aE[mt][1] = cvt_u(xu[(r + g + 8) * XP + cb + t]);
                aE[mt][2] = cvt_u(xu[(r + g)     * XP + cb + t + 4]);
                aE[mt][3] = cvt_u(xu[(r + g + 8) * XP + cb + t + 4]);
                aO[mt][0] = cvt_u(xu[(r + g)     * XP + cb + 8 + t]);
                aO[mt][1] = cvt_u(xu[(r + g + 8) * XP + cb + 8 + t]);
                aO[mt][2] = cvt_u(xu[(r + g)     * XP + cb + 8 + t + 4]);
                aO[mt][3] = cvt_u(xu[(r + g + 8) * XP + cb + 8 + t + 4]);
            }
#pragma unroll
            for (int nt = 0; nt < 8; nt++) {
                int nchunk = wn * 8 + nt;
                float4 bb = w4[(nchunk * 2 + ksp) * 32 + lane];
                mma8(o[0][nt], aE[0], (const unsigned*)&bb.x);
                mma8(o[0][nt], aO[0], (const unsigned*)&bb.z);
                mma8(o[1][nt], aE[1], (const unsigned*)&bb.x);
                mma8(o[1][nt], aO[1], (const unsigned*)&bb.z);
            }
        }
    }

    // ---- epilogue: C-frags -> packed fragment layouts (shuffles hoisted) ----
    const int srcA = (lane & ~3) | (t >> 1);
    const int srcB = srcA + 2;
    const bool selA = (t & 1);
    const int srcV0 = (lane & 3) * 4 + (lane >> 3);
    const int srcV1 = srcV0 + 16;
    const bool selV = ((lane >> 2) & 1);

#pragma unroll
    for (int mt = 0; mt < 2; mt++) {
#pragma unroll
        for (int nt = 0; nt < 8; nt++) {
            float r0, r1, r2, r3;
            if (proj == 0) { r0 = o[mt][nt][0]; r1 = o[mt][nt][1]; r2 = o[mt][nt][2]; r3 = o[mt][nt][3]; }
            else { r0 = to_tf32(o[mt][nt][0]); r1 = to_tf32(o[mt][nt][1]);
                   r2 = to_tf32(o[mt][nt][2]); r3 = to_tf32(o[mt][nt][3]); }
            int dchunk = wn * 8 + nt;

            if (proj == 0) {
                // C -> A frag (quad shuffle), fold softmax scale, round once
                float c0a = __shfl_sync(~0u, r0, srcA), c1a = __shfl_sync(~0u, r1, srcA);
                float c2a = __shfl_sync(~0u, r2, srcA), c3a = __shfl_sync(~0u, r3, srcA);
                float c0b = __shfl_sync(~0u, r0, srcB), c1b = __shfl_sync(~0u, r1, srcB);
                float c2b = __shfl_sync(~0u, r2, srcB), c3b = __shfl_sync(~0u, r3, srcB);
                float4 a;
                a.x = to_tf32((selA ? c1a : c0a) * SCALE);
                a.y = to_tf32((selA ? c3a : c2a) * SCALE);
                a.z = to_tf32((selA ? c1b : c0b) * SCALE);
                a.w = to_tf32((selA ? c3b : c2b) * SCALE);
                int mtile = wm * 2 + mt;
                int ksp = dchunk >> 1, half = dchunk & 1;
                float4* dst = (float4*)g_q + (size_t)rb * 4096 +
                              ((mtile * 8 + ksp) * 32 + lane) * 2 + half;
                *dst = a;
            } else if (proj == 1) {
                // C -> B frag for S-mma  (shuffles hoisted, select after)
                float c0a = __shfl_sync(~0u, r0, srcA), c1a = __shfl_sync(~0u, r1, srcA);
                float c2a = __shfl_sync(~0u, r2, srcA), c3a = __shfl_sync(~0u, r3, srcA);
                float c0b = __shfl_sync(~0u, r0, srcB), c1b = __shfl_sync(~0u, r1, srcB);
                float c2b = __shfl_sync(~0u, r2, srcB), c3b = __shfl_sync(~0u, r3, srcB);
                float b00 = selA ? c1a : c0a;   // K[key0+g      ][d=t]
                float b01 = selA ? c1b : c0b;   // K[key0+g      ][d=t+4]
                float b10 = selA ? c3a : c2a;   // K[key0+8+g    ][d=t]
                float b11 = selA ? c3b : c2b;   // K[key0+8+g    ][d=t+4]
                int key0 = wm * 32 + mt * 16;
                int batch = rb >> 4;
                int ktile = (rb & 15) * 2 + (key0 >> 6);
                int jg0 = (key0 & 63) >> 3;
                int ksp = dchunk >> 1, half = dchunk & 1;
                float2* base = (float2*)g_k + (size_t)(batch * 32 + ktile) * 4096;
                base[((jg0 * 8 + ksp) * 32 + lane) * 2 + half]       = make_float2(b00, b01);
                base[(((jg0 + 1) * 8 + ksp) * 32 + lane) * 2 + half] = make_float2(b10, b11);
            } else {
                // C -> transposed B frag for PV-mma  (shuffles hoisted)
                float d0a = __shfl_sync(~0u, r0, srcV0), d1a = __shfl_sync(~0u, r1, srcV0);
                float d2a = __shfl_sync(~0u, r2, srcV0), d3a = __shfl_sync(~0u, r3, srcV0);
                float d0b = __shfl_sync(~0u, r0, srcV1), d1b = __shfl_sync(~0u, r1, srcV1);
                float d2b = __shfl_sync(~0u, r2, srcV1), d3b = __shfl_sync(~0u, r3, srcV1);
                float b00 = selV ? d1a : d0a;   // V[key0+t   ][d=dchunk*8+g]
                float b01 = selV ? d1b : d0b;   // V[key0+t+4 ][d]
                float b10 = selV ? d3a : d2a;   // V[key0+8+t ][d]
                float b11 = selV ? d3b : d2b;   // V[key0+8+t+4][d]
                int key0 = wm * 32 + mt * 16;
                int batch = rb >> 4;
                int ktile = (rb & 15) * 2 + (key0 >> 6);
                int jg0 = (key0 & 63) >> 3;
                int dp = dchunk >> 1, half = dchunk & 1;
                float2* base = (float2*)g_v + (size_t)(batch * 32 + ktile) * 4096;
                base[((jg0 * 8 + dp) * 32 + lane) * 2 + half]       = make_float2(b00, b01);
                base[(((jg0 + 1) * 8 + dp) * 32 + lane) * 2 + half] = make_float2(b10, b11);
            }
        }
    }
}

// -------------------------------------------------------------------------
// Kernel 2: flash attention, all operands pre-packed as fragments.
// grid=128, block=256 (8 warps x 16 q-rows). 64 keys / iter.
// smem: Q 64KB + K 2x32KB + V 2x32KB = 192KB.
// -------------------------------------------------------------------------
#define Q_F 16384
#define KV_F 8192
#define K_OFF Q_F
#define V_OFF (Q_F + 2 * KV_F)
#define ATTN_SMEM ((Q_F + 4 * KV_F) * 4)   // 196608 B

__global__ __launch_bounds__(256, 1) void attn_mma(float* __restrict__ out) {
    extern __shared__ float sm[];
    unsigned sm_base = (unsigned)__cvta_generic_to_shared(sm);

    const int tid  = threadIdx.x;
    const int warp = tid >> 5;
    const int lane = tid & 31;
    const int g = lane >> 2;
    const int t = lane & 3;

    const int qrow0 = blockIdx.x * 128;
    const int batch = blockIdx.x >> 4;
    const float* kb = g_k + (size_t)batch * 32 * KV_F;
    const float* vb = g_v + (size_t)batch * 32 * KV_F;
    const float* qb = g_q + (size_t)blockIdx.x * Q_F;

    // prefetch Q (once) + K0/V0
#pragma unroll
    for (int i = 0; i < 16; i++) {
        int f = tid + i * 256;
        cp16(sm_base + f * 16, qb + (size_t)f * 4);
    }
#pragma unroll
    for (int i = 0; i < 8; i++) {
        int f = tid + i * 256;
        cp16(sm_base + (K_OFF + f * 4) * 4, kb + (size_t)f * 4);
        cp16(sm_base + (V_OFF + f * 4) * 4, vb + (size_t)f * 4);
    }
    cp_commit();

    float o[16][4];
    float m[2] = {-1e30f, -1e30f}, l[2] = {0.0f, 0.0f};
#pragma unroll
    for (int nt = 0; nt < 16; nt++)
#pragma unroll
        for (int e = 0; e < 4; e++) o[nt][e] = 0.0f;

    const float4* Q4 = (const float4*)sm;

    for (int kt = 0; kt < 32; kt++) {
        __syncthreads();
        if (kt + 1 < 32) {
            int buf = (kt + 1) & 1;
            const float* kq = kb + (size_t)(kt + 1) * KV_F;
            const float* vq = vb + (size_t)(kt + 1) * KV_F;
#pragma unroll
            for (int i = 0; i < 8; i++) {
                int f = tid + i * 256;
                cp16(sm_base + (K_OFF + buf * KV_F + f * 4) * 4, kq + (size_t)f * 4);
                cp16(sm_base + (V_OFF + buf * KV_F + f * 4) * 4, vq + (size_t)f * 4);
            }
        }
        cp_commit();
        cp_wait1();
        __syncthreads();

        const float4* K4 = (const float4*)(sm + K_OFF + (kt & 1) * KV_F);
        const float4* V4 = (const float4*)(sm + V_OFF + (kt & 1) * KV_F);

        // ---- S = Q @ K^T ----
        float s[8][4];
#pragma unroll
        for (int j = 0; j < 8; j++)
#pragma unroll
            for (int e = 0; e < 4; e++) s[j][e] = 0.0f;

#pragma unroll
        for (int ksp = 0; ksp < 8; ksp++) {
            float4 aE = Q4[((warp * 8 + ksp) * 32 + lane) * 2 + 0];
            float4 aO = Q4[((warp * 8 + ksp) * 32 + lane) * 2 + 1];
#pragma unroll
            for (int jg = 0; jg < 8; jg++) {
                float4 bb = K4[(jg * 8 + ksp) * 32 + lane];
                mma8(s[jg], (const unsigned*)&aE, (const unsigned*)&bb.x);
                mma8(s[jg], (const unsigned*)&aO, (const unsigned*)&bb.z);
            }
        }

        // ---- online softmax (log2 domain) ----
        {
            float mx0 = -1e30f, mx1 = -1e30f;
#pragma unroll
            for (int j = 0; j < 8; j++) {
                mx0 = fmaxf(mx0, fmaxf(s[j][0], s[j][1]));
                mx1 = fmaxf(mx1, fmaxf(s[j][2], s[j][3]));
            }
#pragma unroll
            for (int off = 1; off <= 2; off <<= 1) {
                mx0 = fmaxf(mx0, __shfl_xor_sync(~0u, mx0, off));
                mx1 = fmaxf(mx1, __shfl_xor_sync(~0u, mx1, off));
            }
            float mn0 = fmaxf(m[0], mx0), mn1 = fmaxf(m[1], mx1);
            float c0 = exp2f(m[0] - mn0), c1 = exp2f(m[1] - mn1);
            m[0] = mn0; m[1] = mn1;
            float s0 = 0.0f, s1 = 0.0f;
#pragma unroll
            for (int j = 0; j < 8; j++) {
                float p0 = exp2f(s[j][0] - mn0);
                float p1 = exp2f(s[j][1] - mn0);
                float p2 = exp2f(s[j][2] - mn1);
                float p3 = exp2f(s[j][3] - mn1);
                s0 += p0 + p1; s1 += p2 + p3;
                s[j][0] = to_tf32(p0); s[j][1] = to_tf32(p1);
                s[j][2] = to_tf32(p2); s[j][3] = to_tf32(p3);
            }
#pragma unroll
            for (int off = 1; off <= 2; off <<= 1) {
                s0 += __shfl_xor_sync(~0u, s0, off);
                s1 += __shfl_xor_sync(~0u, s1, off);
            }
            l[0] = l[0] * c0 + s0;
            l[1] = l[1] * c1 + s1;
#pragma unroll
            for (int nt = 0; nt < 16; nt++) {
                o[nt][0] *= c0; o[nt][1] *= c0;
                o[nt][2] *= c1; o[nt][3] *= c1;
            }
        }

        // ---- O += P @ V ----
        const int srcA = (lane & ~3) | (t >> 1);
        const int srcB = srcA + 2;
        const bool odd = (t & 1);
#pragma unroll
        for (int jg = 0; jg < 8; jg++) {
            unsigned pa[4];
            {
                float u0 = __shfl_sync(~0u, s[jg][0], srcA);
                float u1 = __shfl_sync(~0u, s[jg][1], srcA);
                float w0 = __shfl_sync(~0u, s[jg][0], srcB);
                float w1 = __shfl_sync(~0u, s[jg][1], srcB);
                float v0 = __shfl_sync(~0u, s[jg][2], srcA);
                float v1 = __shfl_sync(~0u, s[jg][3], srcA);
                float x0 = __shfl_sync(~0u, s[jg][2], srcB);
                float x1 = __shfl_sync(~0u, s[jg][3], srcB);
                pa[0] = __float_as_uint(odd ? u1 : u0);
                pa[1] = __float_as_uint(odd ? v1 : v0);
                pa[2] = __float_as_uint(odd ? w1 : w0);
                pa[3] = __float_as_uint(odd ? x1 : x0);
            }
#pragma unroll
            for (int dp = 0; dp < 8; dp++) {
                float4 bb = V4[(jg * 8 + dp) * 32 + lane];
                mma8(o[2 * dp],     pa, (const unsigned*)&bb.x);
                mma8(o[2 * dp + 1], pa, (const unsigned*)&bb.z);
            }
        }
    }

    // ---- epilogue ----
    {
        float inv0 = 1.0f / l[0];
        float inv1 = 1.0f / l[1];
        size_t r0 = (size_t)qrow0 + warp * 16 + g;
#pragma unroll
        for (int nt = 0; nt < 16; nt++) {
            int c = nt * 8 + 2 * t;
            *(float2*)(out + r0 * HH + c) =
                make_float2(o[nt][0] * inv0, o[nt][1] * inv0);
            *(float2*)(out + (r0 + 8) * HH + c) =
                make_float2(o[nt][2] * inv1, o[nt][3] * inv1);
        }
    }
}

// -------------------------------------------------------------------------
extern "C" void kernel_launch(void* const* d_in, const int* in_sizes, int n_in,
                              void* d_out, int out_size) {
    const float* x  = (const float*)d_in[0];
    const float* Wk = (const float*)d_in[1];
    const float* Wq = (const float*)d_in[2];
    const float* Wv = (const float*)d_in[3];
    float* out = (float*)d_out;

    pack_w<<<384, 256>>>(Wq, Wk, Wv);

    cudaFuncSetAttribute(qkv_mma, cudaFuncAttributeMaxDynamicSharedMemorySize, QKV_SMEM);
    qkv_mma<<<dim3(3, 128), 256, QKV_SMEM>>>(x);

    cudaFuncSetAttribute(attn_mma, cudaFuncAttributeMaxDynamicSharedMemorySize, ATTN_SMEM);
    attn_mma<<<128, 256, ATTN_SMEM>>>(out);
}

// round 7
// speedup vs baseline: 5.5207x; 1.0085x over previous
#include <cuda_runtime.h>

#define BB 8
#define TT 2048
#define CC 1024
#define HH 128

#define SCALE 0.04508422f  /* log2(e) / 32 */

// q: packed A-fragments  [qblock(128)][mtile(8)][ksp(8)][lane(32)][8 floats]
// k: packed B-fragments  [batch(8)][ktile(32)][jg(8)][ksp(8)][lane(32)][4 floats]
// v: packed B-fragments  [batch(8)][ktile(32)][jg(8)][dp(8)][lane(32)][4 floats]
__device__ float g_q[BB*TT*HH];
__device__ float g_k[BB*TT*HH];
__device__ float g_v[BB*TT*HH];
// W packed B-fragments [proj(3)][kt(32)][nchunk(16)][ksp(2)][lane(32)][4 floats]
__device__ float g_w[3*CC*HH];

// -------------------------------------------------------------------------
__device__ __forceinline__ float to_tf32(float x) {
    unsigned u;
    asm("cvt.rna.tf32.f32 %0, %1;" : "=r"(u) : "f"(x));
    return __uint_as_float(u);
}
__device__ __forceinline__ unsigned cvt_u(unsigned x) {
    unsigned u;
    asm("cvt.rna.tf32.f32 %0, %1;" : "=r"(u) : "f"(__uint_as_float(x)));
    return u;
}
__device__ __forceinline__ float ex2(float x) {
    float y;
    asm("ex2.approx.f32 %0, %1;" : "=f"(y) : "f"(x));
    return y;
}
__device__ __forceinline__ void mma8(float* c, const unsigned* A, const unsigned* B) {
    asm volatile(
        "mma.sync.aligned.m16n8k8.row.col.f32.tf32.tf32.f32 "
        "{%0,%1,%2,%3}, {%4,%5,%6,%7}, {%8,%9}, {%0,%1,%2,%3};\n"
        : "+f"(c[0]), "+f"(c[1]), "+f"(c[2]), "+f"(c[3])
        : "r"(A[0]), "r"(A[1]), "r"(A[2]), "r"(A[3]), "r"(B[0]), "r"(B[1]));
}
__device__ __forceinline__ void cp16(unsigned dst, const void* src) {
    asm volatile("cp.async.cg.shared.global [%0], [%1], 16;" :: "r"(dst), "l"(src));
}
__device__ __forceinline__ void cp_commit() { asm volatile("cp.async.commit_group;"); }
__device__ __forceinline__ void cp_wait1()  { asm volatile("cp.async.wait_group 1;"); }

// -------------------------------------------------------------------------
// Prepass: round W to tf32 and pack into B-fragment layout.
// -------------------------------------------------------------------------
__global__ void pack_w(const float* __restrict__ W0, const float* __restrict__ W1,
                       const float* __restrict__ W2) {
    int f = blockIdx.x * 256 + threadIdx.x;
    int lane = f & 31;
    int ksp  = (f >> 5) & 1;
    int nchunk = (f >> 6) & 15;
    int kt = (f >> 10) & 31;
    int y  = f >> 15;
    const float* W = (y == 0) ? W0 : (y == 1) ? W1 : W2;
    int g = lane >> 2, t = lane & 3;
    int ke = kt * 32 + ksp * 16;
    int col = nchunk * 8 + g;
    float4 o;
    o.x = to_tf32(W[(size_t)(ke + t)     * HH + col]);
    o.y = to_tf32(W[(size_t)(ke + t + 4) * HH + col]);
    o.z = to_tf32(W[(size_t)(ke + 8 + t)     * HH + col]);
    o.w = to_tf32(W[(size_t)(ke + 8 + t + 4) * HH + col]);
    *(float4*)(g_w + (size_t)f * 4) = o;
}

// -------------------------------------------------------------------------
// Kernel 1: QKV projection (round-6 verbatim, known good).
// -------------------------------------------------------------------------
#define XP 36
#define XBUF (128 * XP)
#define WTILE 4096
#define QKV_SMEM ((2 * XBUF + 2 * WTILE) * 4)   // 69632 B

__global__ __launch_bounds__(256, 2) void qkv_mma(const float* __restrict__ x) {
    extern __shared__ float sm[];
    float* xs = sm;
    float* ws = sm + 2 * XBUF;
    unsigned sm_base = (unsigned)__cvta_generic_to_shared(sm);

    const int tid  = threadIdx.x;
    const int warp = tid >> 5;
    const int lane = tid & 31;
    const int g = lane >> 2;
    const int t = lane & 3;
    const int wm = warp >> 1;
    const int wn = warp & 1;
    const int proj = blockIdx.x;    // 0=q 1=k 2=v
    const int rb   = blockIdx.y;

    const float* xb = x + (size_t)rb * 128 * CC;
    const float* wb = g_w + (size_t)proj * 32 * WTILE;

    auto issue_x = [&](int buf, int k0) {
#pragma unroll
        for (int i = 0; i < 4; i++) {
            int f = tid + i * 256;
            int row = f >> 3, c4 = f & 7;
            cp16(sm_base + (buf * XBUF + row * XP + c4 * 4) * 4,
                 xb + (size_t)row * CC + k0 + c4 * 4);
        }
    };
    auto issue_w = [&](int buf, int kt) {
#pragma unroll
        for (int i = 0; i < 4; i++) {
            int f = tid + i * 256;
            cp16(sm_base + (2 * XBUF + buf * WTILE + f * 4) * 4,
                 wb + (size_t)kt * WTILE + f * 4);
        }
    };

    float o[2][8][4];
#pragma unroll
    for (int mt = 0; mt < 2; mt++)
#pragma unroll
        for (int nt = 0; nt < 8; nt++)
#pragma unroll
            for (int e = 0; e < 4; e++) o[mt][nt][e] = 0.0f;

    issue_x(0, 0);
    issue_w(0, 0);
    cp_commit();

    for (int kt = 0; kt < 32; kt++) {
        __syncthreads();
        if (kt + 1 < 32) { issue_x((kt + 1) & 1, (kt + 1) * 32); issue_w((kt + 1) & 1, kt + 1); }
        cp_commit();
        cp_wait1();
        __syncthreads();

        const unsigned* xu = (const unsigned*)(xs + (kt & 1) * XBUF);
        const float4*   w4 = (const float4*)(ws + (kt & 1) * WTILE);

#pragma unroll
        for (int ksp = 0; ksp < 2; ksp++) {
            unsigned aE[2][4], aO[2][4];
#pragma unroll
            for (int mt = 0; mt < 2; mt++) {
                int r = wm * 32 + mt * 16;
                int cb = ksp * 16;
                aE[mt][0] = cvt_u(xu[(r + g)     * XP + cb + t]);
                aE[mt][1] = cvt_u(xu[(r + g + 8) * XP + cb + t]);
                aE[mt][2] = cvt_u(xu[(r + g)     * XP + cb + t + 4]);
                aE[mt][3] = cvt_u(xu[(r + g + 8) * XP + cb + t + 4]);
                aO[mt][0] = cvt_u(xu[(r + g)     * XP + cb + 8 + t]);
                aO[mt][1] = cvt_u(xu[(r + g + 8) * XP + cb + 8 + t]);
                aO[mt][2] = cvt_u(xu[(r + g)     * XP + cb + 8 + t + 4]);
                aO[mt][3] = cvt_u(xu[(r + g + 8) * XP + cb + 8 + t + 4]);
            }
#pragma unroll
            for (int nt = 0; nt < 8; nt++) {
                int nchunk = wn * 8 + nt;
                float4 bb = w4[(nchunk * 2 + ksp) * 32 + lane];
                mma8(o[0][nt], aE[0], (const unsigned*)&bb.x);
                mma8(o[0][nt], aO[0], (const unsigned*)&bb.z);
                mma8(o[1][nt], aE[1], (const unsigned*)&bb.x);
                mma8(o[1][nt], aO[1], (const unsigned*)&bb.z);
            }
        }
    }

    // ---- epilogue: C-frags -> packed fragment layouts (shuffles hoisted) ----
    const int srcA = (lane & ~3) | (t >> 1);
    const int srcB = srcA + 2;
    const bool selA = (t & 1);
    const int srcV0 = (lane & 3) * 4 + (lane >> 3);
    const int srcV1 = srcV0 + 16;
    const bool selV = ((lane >> 2) & 1);

#pragma unroll
    for (int mt = 0; mt < 2; mt++) {
#pragma unroll
        for (int nt = 0; nt < 8; nt++) {
            float r0, r1, r2, r3;
            if (proj == 0) { r0 = o[mt][nt][0]; r1 = o[mt][nt][1]; r2 = o[mt][nt][2]; r3 = o[mt][nt][3]; }
            else { r0 = to_tf32(o[mt][nt][0]); r1 = to_tf32(o[mt][nt][1]);
                   r2 = to_tf32(o[mt][nt][2]); r3 = to_tf32(o[mt][nt][3]); }
            int dchunk = wn * 8 + nt;

            if (proj == 0) {
                float c0a = __shfl_sync(~0u, r0, srcA), c1a = __shfl_sync(~0u, r1, srcA);
                float c2a = __shfl_sync(~0u, r2, srcA), c3a = __shfl_sync(~0u, r3, srcA);
                float c0b = __shfl_sync(~0u, r0, srcB), c1b = __shfl_sync(~0u, r1, srcB);
                float c2b = __shfl_sync(~0u, r2, srcB), c3b = __shfl_sync(~0u, r3, srcB);
                float4 a;
                a.x = to_tf32((selA ? c1a : c0a) * SCALE);
                a.y = to_tf32((selA ? c3a : c2a) * SCALE);
                a.z = to_tf32((selA ? c1b : c0b) * SCALE);
                a.w = to_tf32((selA ? c3b : c2b) * SCALE);
                int mtile = wm * 2 + mt;
                int ksp = dchunk >> 1, half = dchunk & 1;
                float4* dst = (float4*)g_q + (size_t)rb * 4096 +
                              ((mtile * 8 + ksp) * 32 + lane) * 2 + half;
                *dst = a;
            } else if (proj == 1) {
                float c0a = __shfl_sync(~0u, r0, srcA), c1a = __shfl_sync(~0u, r1, srcA);
                float c2a = __shfl_sync(~0u, r2, srcA), c3a = __shfl_sync(~0u, r3, srcA);
                float c0b = __shfl_sync(~0u, r0, srcB), c1b = __shfl_sync(~0u, r1, srcB);
                float c2b = __shfl_sync(~0u, r2, srcB), c3b = __shfl_sync(~0u, r3, srcB);
                float b00 = selA ? c1a : c0a;
                float b01 = selA ? c1b : c0b;
                float b10 = selA ? c3a : c2a;
                float b11 = selA ? c3b : c2b;
                int key0 = wm * 32 + mt * 16;
                int batch = rb >> 4;
                int ktile = (rb & 15) * 2 + (key0 >> 6);
                int jg0 = (key0 & 63) >> 3;
                int ksp = dchunk >> 1, half = dchunk & 1;
                float2* base = (float2*)g_k + (size_t)(batch * 32 + ktile) * 4096;
                base[((jg0 * 8 + ksp) * 32 + lane) * 2 + half]       = make_float2(b00, b01);
                base[(((jg0 + 1) * 8 + ksp) * 32 + lane) * 2 + half] = make_float2(b10, b11);
            } else {
                float d0a = __shfl_sync(~0u, r0, srcV0), d1a = __shfl_sync(~0u, r1, srcV0);
                float d2a = __shfl_sync(~0u, r2, srcV0), d3a = __shfl_sync(~0u, r3, srcV0);
                float d0b = __shfl_sync(~0u, r0, srcV1), d1b = __shfl_sync(~0u, r1, srcV1);
                float d2b = __shfl_sync(~0u, r2, srcV1), d3b = __shfl_sync(~0u, r3, srcV1);
                float b00 = selV ? d1a : d0a;
                float b01 = selV ? d1b : d0b;
                float b10 = selV ? d3a : d2a;
                float b11 = selV ? d3b : d2b;
                int key0 = wm * 32 + mt * 16;
                int batch = rb >> 4;
                int ktile = (rb & 15) * 2 + (key0 >> 6);
                int jg0 = (key0 & 63) >> 3;
                int dp = dchunk >> 1, half = dchunk & 1;
                float2* base = (float2*)g_v + (size_t)(batch * 32 + ktile) * 4096;
                base[((jg0 * 8 + dp) * 32 + lane) * 2 + half]       = make_float2(b00, b01);
                base[(((jg0 + 1) * 8 + dp) * 32 + lane) * 2 + half] = make_float2(b10, b11);
            }
        }
    }
}

// -------------------------------------------------------------------------
// Kernel 2: flash attention, paired K-tiles (128-key softmax period).
// grid=128, block=256 (8 warps x 16 q-rows).
// smem: Q 64KB + K pair 64KB + V pair 64KB = 192KB (alternating reload).
// Pipeline: V(p) loads overlap S(p); K(p+1) loads overlap softmax+PV(p).
// -------------------------------------------------------------------------
#define Q_F 16384
#define KV_F 8192
#define K_OFF Q_F
#define V_OFF (Q_F + 2 * KV_F)
#define ATTN_SMEM ((Q_F + 4 * KV_F) * 4)   // 196608 B

__global__ __launch_bounds__(256, 1) void attn_mma(float* __restrict__ out) {
    extern __shared__ float sm[];
    unsigned sm_base = (unsigned)__cvta_generic_to_shared(sm);

    const int tid  = threadIdx.x;
    const int warp = tid >> 5;
    const int lane = tid & 31;
    const int g = lane >> 2;
    const int t = lane & 3;

    const int qrow0 = blockIdx.x * 128;
    const int batch = blockIdx.x >> 4;
    const float* kb = g_k + (size_t)batch * 32 * KV_F;
    const float* vb = g_v + (size_t)batch * 32 * KV_F;
    const float* qb = g_q + (size_t)blockIdx.x * Q_F;

    // pair loads: tiles 2p, 2p+1 are contiguous (16384 floats)
    auto issue_kpair = [&](int p) {
        const float* src = kb + (size_t)p * 2 * KV_F;
#pragma unroll
        for (int i = 0; i < 16; i++) {
            int f = tid + i * 256;
            cp16(sm_base + (K_OFF + f * 4) * 4, src + (size_t)f * 4);
        }
    };
    auto issue_vpair = [&](int p) {
        const float* src = vb + (size_t)p * 2 * KV_F;
#pragma unroll
        for (int i = 0; i < 16; i++) {
            int f = tid + i * 256;
            cp16(sm_base + (V_OFF + f * 4) * 4, src + (size_t)f * 4);
        }
    };

    // group 1: Q + K pair 0;  group 2: V pair 0
#pragma unroll
    for (int i = 0; i < 16; i++) {
        int f = tid + i * 256;
        cp16(sm_base + f * 16, qb + (size_t)f * 4);
    }
    issue_kpair(0);
    cp_commit();
    issue_vpair(0);
    cp_commit();

    float o[16][4];
    float m[2] = {-1e30f, -1e30f}, l[2] = {0.0f, 0.0f};
#pragma unroll
    for (int nt = 0; nt < 16; nt++)
#pragma unroll
        for (int e = 0; e < 4; e++) o[nt][e] = 0.0f;

    const float4* Q4 = (const float4*)sm;
    const int srcA = (lane & ~3) | (t >> 1);
    const int srcB = srcA + 2;
    const bool odd = (t & 1);

    for (int p = 0; p < 16; p++) {
        cp_wait1();          // Q+K pair p resident (V pair may still be in flight)
        __syncthreads();

        // ---- S = Q @ K^T over 128 keys (two 64-key halves) ----
        float s[16][4];
#pragma unroll
        for (int j = 0; j < 16; j++)
#pragma unroll
            for (int e = 0; e < 4; e++) s[j][e] = 0.0f;

#pragma unroll
        for (int h = 0; h < 2; h++) {
            const float4* K4 = (const float4*)(sm + K_OFF + h * KV_F);
#pragma unroll
            for (int ksp = 0; ksp < 8; ksp++) {
                float4 aE = Q4[((warp * 8 + ksp) * 32 + lane) * 2 + 0];
                float4 aO = Q4[((warp * 8 + ksp) * 32 + lane) * 2 + 1];
#pragma unroll
                for (int jg = 0; jg < 8; jg++) {
                    float4 bb = K4[(jg * 8 + ksp) * 32 + lane];
                    mma8(s[h * 8 + jg], (const unsigned*)&aE, (const unsigned*)&bb.x);
                    mma8(s[h * 8 + jg], (const unsigned*)&aO, (const unsigned*)&bb.z);
                }
            }
        }
        __syncthreads();     // all warps done reading K bufs

        // prefetch next K pair (overlaps softmax + PV)
        if (p + 1 < 16) issue_kpair(p + 1);
        cp_commit();

        // ---- softmax over 128 keys (regs only) ----
        {
            float mx0 = -1e30f, mx1 = -1e30f;
#pragma unroll
            for (int j = 0; j < 16; j++) {
                mx0 = fmaxf(mx0, fmaxf(s[j][0], s[j][1]));
                mx1 = fmaxf(mx1, fmaxf(s[j][2], s[j][3]));
            }
#pragma unroll
            for (int off = 1; off <= 2; off <<= 1) {
                mx0 = fmaxf(mx0, __shfl_xor_sync(~0u, mx0, off));
                mx1 = fmaxf(mx1, __shfl_xor_sync(~0u, mx1, off));
            }
            bool need = (mx0 > m[0]) || (mx1 > m[1]);   // exact: c==1 when false
            float mn0 = fmaxf(m[0], mx0), mn1 = fmaxf(m[1], mx1);
            float c0 = ex2(m[0] - mn0), c1 = ex2(m[1] - mn1);
            m[0] = mn0; m[1] = mn1;
            float s0 = 0.0f, s1 = 0.0f;
#pragma unroll
            for (int j = 0; j < 16; j++) {
                float p0 = ex2(s[j][0] - mn0);
                float p1 = ex2(s[j][1] - mn0);
                float p2 = ex2(s[j][2] - mn1);
                float p3 = ex2(s[j][3] - mn1);
                s0 += p0 + p1; s1 += p2 + p3;
                s[j][0] = to_tf32(p0); s[j][1] = to_tf32(p1);
                s[j][2] = to_tf32(p2); s[j][3] = to_tf32(p3);
            }
#pragma unroll
            for (int off = 1; off <= 2; off <<= 1) {
                s0 += __shfl_xor_sync(~0u, s0, off);
                s1 += __shfl_xor_sync(~0u, s1, off);
            }
            l[0] = l[0] * c0 + s0;
            l[1] = l[1] * c1 + s1;
            if (need) {
#pragma unroll
                for (int nt = 0; nt < 16; nt++) {
                    o[nt][0] *= c0; o[nt][1] *= c0;
                    o[nt][2] *= c1; o[nt][3] *= c1;
                }
            }
        }

        cp_wait1();          // V pair p resident (K pair p+1 in flight)
        __syncthreads();

        // ---- O += P @ V over both halves ----
#pragma unroll
        for (int h = 0; h < 2; h++) {
            const float4* V4 = (const float4*)(sm + V_OFF + h * KV_F);
#pragma unroll
            for (int jg = 0; jg < 8; jg++) {
                unsigned pa[4];
                {
                    float* sj = s[h * 8 + jg];
                    float u0 = __shfl_sync(~0u, sj[0], srcA);
                    float u1 = __shfl_sync(~0u, sj[1], srcA);
                    float w0 = __shfl_sync(~0u, sj[0], srcB);
                    float w1 = __shfl_sync(~0u, sj[1], srcB);
                    float v0 = __shfl_sync(~0u, sj[2], srcA);
                    float v1 = __shfl_sync(~0u, sj[3], srcA);
                    float x0 = __shfl_sync(~0u, sj[2], srcB);
                    float x1 = __shfl_sync(~0u, sj[3], srcB);
                    pa[0] = __float_as_uint(odd ? u1 : u0);
                    pa[1] = __float_as_uint(odd ? v1 : v0);
                    pa[2] = __float_as_uint(odd ? w1 : w0);
                    pa[3] = __float_as_uint(odd ? x1 : x0);
                }
#pragma unroll
                for (int dp = 0; dp < 8; dp++) {
                    float4 bb = V4[(jg * 8 + dp) * 32 + lane];
                    mma8(o[2 * dp],     pa, (const unsigned*)&bb.x);
                    mma8(o[2 * dp + 1], pa, (const unsigned*)&bb.z);
                }
            }
        }
        __syncthreads();     // all warps done reading V bufs

        // prefetch next V pair (overlaps next S phase)
        if (p + 1 < 16) issue_vpair(p + 1);
        cp_commit();
    }

    // ---- epilogue ----
    {
        float inv0 = 1.0f / l[0];
        float inv1 = 1.0f / l[1];
        size_t r0 = (size_t)qrow0 + warp * 16 + g;
#pragma unroll
        for (int nt = 0; nt < 16; nt++) {
            int c = nt * 8 + 2 * t;
            *(float2*)(out + r0 * HH + c) =
                make_float2(o[nt][0] * inv0, o[nt][1] * inv0);
            *(float2*)(out + (r0 + 8) * HH + c) =
                make_float2(o[nt][2] * inv1, o[nt][3] * inv1);
        }
    }
}

// -------------------------------------------------------------------------
extern "C" void kernel_launch(void* const* d_in, const int* in_sizes, int n_in,
                              void* d_out, int out_size) {
    const float* x  = (const float*)d_in[0];
    const float* Wk = (const float*)d_in[1];
    const float* Wq = (const float*)d_in[2];
    const float* Wv = (const float*)d_in[3];
    float* out = (float*)d_out;

    pack_w<<<384, 256>>>(Wq, Wk, Wv);

    cudaFuncSetAttribute(qkv_mma, cudaFuncAttributeMaxDynamicSharedMemorySize, QKV_SMEM);
    qkv_mma<<<dim3(3, 128), 256, QKV_SMEM>>>(x);

    cudaFuncSetAttribute(attn_mma, cudaFuncAttributeMaxDynamicSharedMemorySize, ATTN_SMEM);
    attn_mma<<<128, 256, ATTN_SMEM>>>(out);
}